// round 2
// baseline (speedup 1.0000x reference)
#include <cuda_runtime.h>

typedef unsigned long long ULL;

#define N_   16
#define C_   384
#define S_   1024
#define NH_  6
#define D_   64
#define C3_  1152
#define M_   (N_*S_)

// ---------------- scratch (device globals; no allocation) ----------------
__device__ float g_wqkvT[C_*C3_];         // [384][1152]
__device__ float g_woutT[C_*C_];          // [384][384]
__device__ float g_q[N_*NH_*S_*D_];       // [n*6+h][s][d], pre-scaled
__device__ float g_k[N_*NH_*S_*D_];
__device__ float g_v[N_*NH_*S_*D_];
__device__ float g_ao[N_*S_*C_];          // attention output, [n][s][c]

// ---------------- packed f32x2 helpers (full-rate fp32 on sm_103a) -------
__device__ __forceinline__ ULL pack2(float lo, float hi) {
    ULL r; asm("mov.b64 %0, {%1, %2};" : "=l"(r) : "f"(lo), "f"(hi)); return r;
}
__device__ __forceinline__ float2 unpack2(ULL a) {
    float2 f; asm("mov.b64 {%0, %1}, %2;" : "=f"(f.x), "=f"(f.y) : "l"(a)); return f;
}
__device__ __forceinline__ ULL fma2(ULL a, ULL b, ULL c) {
    ULL d; asm("fma.rn.f32x2 %0, %1, %2, %3;" : "=l"(d) : "l"(a), "l"(b), "l"(c)); return d;
}
__device__ __forceinline__ ULL mul2(ULL a, ULL b) {
    ULL d; asm("mul.rn.f32x2 %0, %1, %2;" : "=l"(d) : "l"(a), "l"(b)); return d;
}
__device__ __forceinline__ ULL add2(ULL a, ULL b) {
    ULL d; asm("add.rn.f32x2 %0, %1, %2;" : "=l"(d) : "l"(a), "l"(b)); return d;
}

// ---------------- weight transposes ----------------
__global__ void transpose_wqkv(const float* __restrict__ w) {
    int idx = blockIdx.x * 256 + threadIdx.x;
    if (idx < C3_ * C_) {
        int r = idx / C_, k = idx % C_;
        g_wqkvT[k * C3_ + r] = w[idx];
    }
}
__global__ void transpose_wout(const float* __restrict__ w) {
    int idx = blockIdx.x * 256 + threadIdx.x;
    if (idx < C_ * C_) {
        int c = idx / C_, k = idx % C_;
        g_woutT[k * C_ + c] = w[idx];
    }
}

// ---------------- QKV projection ----------------
__global__ __launch_bounds__(256) void qkv_gemm(const float* __restrict__ x) {
    __shared__ float As[16][64];
    __shared__ float Bs[16][128];

    int tid = threadIdx.x;
    int m0 = blockIdx.y * 64;
    int r0 = blockIdx.x * 128;
    int n  = m0 / S_;
    int s0 = m0 % S_;
    int ty = tid / 16;
    int tx = tid % 16;

    ULL acc[4][4];
    #pragma unroll
    for (int i = 0; i < 4; i++)
        #pragma unroll
        for (int j = 0; j < 4; j++) acc[i][j] = 0ull;

    for (int k0 = 0; k0 < C_; k0 += 16) {
        __syncthreads();
        { // A tile: 64x16, coalesced along s
            int m4 = tid % 16;
            int kk = tid / 16;
            const float* src = x + (size_t)n * C_ * S_ + (size_t)(k0 + kk) * S_ + s0 + m4 * 4;
            *(float4*)&As[kk][m4 * 4] = *(const float4*)src;
        }
        { // B tile: 16x128, coalesced along r
            int r4 = tid % 32;
            int kk = tid / 32;
            #pragma unroll
            for (int p = 0; p < 2; p++) {
                const float* src = g_wqkvT + (size_t)(k0 + kk + p * 8) * C3_ + r0 + r4 * 4;
                *(float4*)&Bs[kk + p * 8][r4 * 4] = *(const float4*)src;
            }
        }
        __syncthreads();

        #pragma unroll
        for (int k = 0; k < 16; k++) {
            float4 a4 = *(const float4*)&As[k][ty * 4];
            ULL ad0 = pack2(a4.x, a4.x), ad1 = pack2(a4.y, a4.y);
            ULL ad2 = pack2(a4.z, a4.z), ad3 = pack2(a4.w, a4.w);
            const ulonglong2* brow = (const ulonglong2*)&Bs[k][tx * 8];
            ulonglong2 bA = brow[0], bB = brow[1];       // 2x LDS.128
            ULL b0 = bA.x, b1 = bA.y, b2 = bB.x, b3 = bB.y;
            acc[0][0] = fma2(ad0, b0, acc[0][0]); acc[0][1] = fma2(ad0, b1, acc[0][1]);
            acc[0][2] = fma2(ad0, b2, acc[0][2]); acc[0][3] = fma2(ad0, b3, acc[0][3]);
            acc[1][0] = fma2(ad1, b0, acc[1][0]); acc[1][1] = fma2(ad1, b1, acc[1][1]);
            acc[1][2] = fma2(ad1, b2, acc[1][2]); acc[1][3] = fma2(ad1, b3, acc[1][3]);
            acc[2][0] = fma2(ad2, b0, acc[2][0]); acc[2][1] = fma2(ad2, b1, acc[2][1]);
            acc[2][2] = fma2(ad2, b2, acc[2][2]); acc[2][3] = fma2(ad2, b3, acc[2][3]);
            acc[3][0] = fma2(ad3, b0, acc[3][0]); acc[3][1] = fma2(ad3, b1, acc[3][1]);
            acc[3][2] = fma2(ad3, b2, acc[3][2]); acc[3][3] = fma2(ad3, b3, acc[3][3]);
        }
    }

    const float scale = 0.125f;  // 1/sqrt(64), folded into Q
    #pragma unroll
    for (int mi = 0; mi < 4; mi++) {
        int s = s0 + ty * 4 + mi;
        #pragma unroll
        for (int rp = 0; rp < 4; rp++) {
            float2 v = unpack2(acc[mi][rp]);
            int rbase = r0 + tx * 8 + rp * 2;
            #pragma unroll
            for (int lane = 0; lane < 2; lane++) {
                int r = rbase + lane;
                int t = r / C_;
                int f = r % C_;
                int h = f / D_;
                int d = f % D_;
                float val = lane ? v.y : v.x;
                float* dst;
                if (t == 0)      { dst = g_q; val *= scale; }
                else if (t == 1) { dst = g_k; }
                else             { dst = g_v; }
                dst[(((size_t)(n * NH_ + h)) * S_ + s) * D_ + d] = val;
            }
        }
    }
}

// ---------------- flash attention ----------------
// One thread = one query row. Q and O in registers (f32x2), K/V tiles (32 keys)
// in smem read via LDS.128 broadcast (2 fma2 per shared load), online softmax
// with rescale skipped when the running max doesn't change.
__global__ __launch_bounds__(128) void attn_kernel() {
    __shared__ float Ks[32][64];
    __shared__ float Vs[32][64];
    __shared__ float Sc[128][33];   // padded score staging

    int nh  = blockIdx.y;
    int tid = threadIdx.x;
    int q_idx = blockIdx.x * 128 + tid;

    const float* qptr = g_q + ((size_t)nh * S_ + q_idx) * D_;
    ULL q2[32];
    #pragma unroll
    for (int i = 0; i < 16; i++) {
        float4 t4 = *(const float4*)(qptr + i * 4);
        q2[2 * i]     = pack2(t4.x, t4.y);
        q2[2 * i + 1] = pack2(t4.z, t4.w);
    }

    ULL o2[32];
    #pragma unroll
    for (int i = 0; i < 32; i++) o2[i] = 0ull;
    float mrun = -1e30f, lrun = 0.0f;

    const float* kbase = g_k + (size_t)nh * S_ * D_;
    const float* vbase = g_v + (size_t)nh * S_ * D_;

    for (int kt = 0; kt < 32; kt++) {
        __syncthreads();
        #pragma unroll
        for (int i = 0; i < 4; i++) {
            int f = i * 128 + tid;
            int row = f >> 4, c4 = f & 15;
            size_t g = (size_t)(kt * 32 + row) * D_ + c4 * 4;
            *(float4*)&Ks[row][c4 * 4] = *(const float4*)(kbase + g);
            *(float4*)&Vs[row][c4 * 4] = *(const float4*)(vbase + g);
        }
        __syncthreads();

        // ---- scores: q . k_j via LDS.128 (ulonglong2) ----
        float tmax = -1e30f;
        #pragma unroll 4
        for (int j = 0; j < 32; j++) {
            const ulonglong2* kr = (const ulonglong2*)&Ks[j][0];  // 16 x LDS.128
            ULL a0 = 0ull, a1 = 0ull, a2 = 0ull, a3 = 0ull;
            #pragma unroll
            for (int i = 0; i < 16; i += 2) {
                ulonglong2 kA = kr[i];
                ulonglong2 kB = kr[i + 1];
                a0 = fma2(q2[2 * i],     kA.x, a0);
                a1 = fma2(q2[2 * i + 1], kA.y, a1);
                a2 = fma2(q2[2 * i + 2], kB.x, a2);
                a3 = fma2(q2[2 * i + 3], kB.y, a3);
            }
            ULL at = add2(add2(a0, a1), add2(a2, a3));
            float2 u = unpack2(at);
            float sj = u.x + u.y;
            Sc[tid][j] = sj;
            tmax = fmaxf(tmax, sj);
        }

        // ---- online softmax rescale (skip when max unchanged) ----
        if (tmax > mrun) {
            float corr = __expf(mrun - tmax);
            lrun *= corr;
            ULL cd = pack2(corr, corr);
            #pragma unroll
            for (int i = 0; i < 32; i++) o2[i] = mul2(o2[i], cd);
            mrun = tmax;
        }

        // ---- P.V accumulate via LDS.128 ----
        #pragma unroll 4
        for (int j = 0; j < 32; j++) {
            float p = __expf(Sc[tid][j] - mrun);
            lrun += p;
            ULL pd = pack2(p, p);
            const ulonglong2* vr = (const ulonglong2*)&Vs[j][0];  // 16 x LDS.128
            #pragma unroll
            for (int i = 0; i < 16; i++) {
                ulonglong2 vv = vr[i];
                o2[2 * i]     = fma2(pd, vv.x, o2[2 * i]);
                o2[2 * i + 1] = fma2(pd, vv.y, o2[2 * i + 1]);
            }
        }
    }

    float inv = 1.0f / lrun;
    ULL iv = pack2(inv, inv);
    int n = nh / NH_, h = nh % NH_;
    float* dst = g_ao + ((size_t)(n * S_ + q_idx)) * C_ + h * D_;
    #pragma unroll
    for (int i = 0; i < 16; i++) {
        float2 lo = unpack2(mul2(o2[2 * i], iv));
        float2 hi = unpack2(mul2(o2[2 * i + 1], iv));
        float4 w = make_float4(lo.x, lo.y, hi.x, hi.y);
        *(float4*)(dst + i * 4) = w;
    }
}

// ---------------- output projection + bias + transpose to [N,C,H,W] -------
__global__ __launch_bounds__(256) void proj_gemm(const float* __restrict__ bias,
                                                 float* __restrict__ out) {
    __shared__ float As[64][16];
    __shared__ float Bs[16][128];

    int tid = threadIdx.x;
    int m0 = blockIdx.y * 64;
    int c0 = blockIdx.x * 128;
    int n  = m0 / S_;
    int s0 = m0 % S_;
    int ty = tid / 16;
    int tx = tid % 16;

    ULL acc[4][4];
    #pragma unroll
    for (int i = 0; i < 4; i++)
        #pragma unroll
        for (int j = 0; j < 4; j++) acc[i][j] = 0ull;

    for (int k0 = 0; k0 < C_; k0 += 16) {
        __syncthreads();
        {
            int k4 = tid % 4;
            int m  = tid / 4;
            const float* src = g_ao + (size_t)(m0 + m) * C_ + k0 + k4 * 4;
            *(float4*)&As[m][k4 * 4] = *(const float4*)src;
        }
        {
            int r4 = tid % 32;
            int kk = tid / 32;
            #pragma unroll
            for (int p = 0; p < 2; p++) {
                const float* src = g_woutT + (size_t)(k0 + kk + p * 8) * C_ + c0 + r4 * 4;
                *(float4*)&Bs[kk + p * 8][r4 * 4] = *(const float4*)src;
            }
        }
        __syncthreads();

        #pragma unroll
        for (int k = 0; k < 16; k++) {
            float a0 = As[ty * 4 + 0][k];
            float a1 = As[ty * 4 + 1][k];
            float a2 = As[ty * 4 + 2][k];
            float a3 = As[ty * 4 + 3][k];
            ULL ad0 = pack2(a0, a0), ad1 = pack2(a1, a1);
            ULL ad2 = pack2(a2, a2), ad3 = pack2(a3, a3);
            const ulonglong2* brow = (const ulonglong2*)&Bs[k][tx * 8];
            ulonglong2 bA = brow[0], bB = brow[1];
            ULL b0 = bA.x, b1 = bA.y, b2 = bB.x, b3 = bB.y;
            acc[0][0] = fma2(ad0, b0, acc[0][0]); acc[0][1] = fma2(ad0, b1, acc[0][1]);
            acc[0][2] = fma2(ad0, b2, acc[0][2]); acc[0][3] = fma2(ad0, b3, acc[0][3]);
            acc[1][0] = fma2(ad1, b0, acc[1][0]); acc[1][1] = fma2(ad1, b1, acc[1][1]);
            acc[1][2] = fma2(ad1, b2, acc[1][2]); acc[1][3] = fma2(ad1, b3, acc[1][3]);
            acc[2][0] = fma2(ad2, b0, acc[2][0]); acc[2][1] = fma2(ad2, b1, acc[2][1]);
            acc[2][2] = fma2(ad2, b2, acc[2][2]); acc[2][3] = fma2(ad2, b3, acc[2][3]);
            acc[3][0] = fma2(ad3, b0, acc[3][0]); acc[3][1] = fma2(ad3, b1, acc[3][1]);
            acc[3][2] = fma2(ad3, b2, acc[3][2]); acc[3][3] = fma2(ad3, b3, acc[3][3]);
        }
    }

    #pragma unroll
    for (int mi = 0; mi < 4; mi++) {
        int s = s0 + ty * 4 + mi;
        #pragma unroll
        for (int rp = 0; rp < 4; rp++) {
            float2 v = unpack2(acc[mi][rp]);
            int c = c0 + tx * 8 + rp * 2;
            out[(size_t)n * C_ * S_ + (size_t)c * S_ + s]       = v.x + bias[c];
            out[(size_t)n * C_ * S_ + (size_t)(c + 1) * S_ + s] = v.y + bias[c + 1];
        }
    }
}

// ---------------- launch ----------------
extern "C" void kernel_launch(void* const* d_in, const int* in_sizes, int n_in,
                              void* d_out, int out_size) {
    const float* x     = (const float*)d_in[0];
    const float* w_qkv = (const float*)d_in[1];
    const float* w_out = (const float*)d_in[2];
    const float* b_out = (const float*)d_in[3];
    float* out = (float*)d_out;

    transpose_wqkv<<<(C3_ * C_ + 255) / 256, 256>>>(w_qkv);
    transpose_wout<<<(C_ * C_ + 255) / 256, 256>>>(w_out);

    qkv_gemm<<<dim3(C3_ / 128, M_ / 64), 256>>>(x);

    attn_kernel<<<dim3(S_ / 128, N_ * NH_), 128>>>();

    proj_gemm<<<dim3(C_ / 128, M_ / 64), 256>>>(b_out, out);
}

// round 3
// speedup vs baseline: 1.2180x; 1.2180x over previous
#include <cuda_runtime.h>

typedef unsigned long long ULL;

#define N_   16
#define C_   384
#define S_   1024
#define NH_  6
#define D_   64
#define C3_  1152
#define M_   (N_*S_)

// ---------------- scratch (device globals; no allocation) ----------------
__device__ float g_wqkvT[C_*C3_];         // [384][1152]
__device__ float g_woutT[C_*C_];          // [384][384]
__device__ float g_q[N_*NH_*S_*D_];       // [n*6+h][s][d], pre-scaled
__device__ float g_k[N_*NH_*S_*D_];
__device__ float g_v[N_*NH_*S_*D_];
__device__ float g_ao[N_*S_*C_];          // attention output, [n][s][c]

// ---------------- packed f32x2 helpers ----------------
__device__ __forceinline__ ULL pack2(float lo, float hi) {
    ULL r; asm("mov.b64 %0, {%1, %2};" : "=l"(r) : "f"(lo), "f"(hi)); return r;
}
__device__ __forceinline__ float2 unpack2(ULL a) {
    float2 f; asm("mov.b64 {%0, %1}, %2;" : "=f"(f.x), "=f"(f.y) : "l"(a)); return f;
}
__device__ __forceinline__ ULL fma2(ULL a, ULL b, ULL c) {
    ULL d; asm("fma.rn.f32x2 %0, %1, %2, %3;" : "=l"(d) : "l"(a), "l"(b), "l"(c)); return d;
}
__device__ __forceinline__ ULL mul2(ULL a, ULL b) {
    ULL d; asm("mul.rn.f32x2 %0, %1, %2;" : "=l"(d) : "l"(a), "l"(b)); return d;
}

// ---------------- weight transposes ----------------
__global__ void transpose_wqkv(const float* __restrict__ w) {
    int idx = blockIdx.x * 256 + threadIdx.x;
    if (idx < C3_ * C_) {
        int r = idx / C_, k = idx % C_;
        g_wqkvT[k * C3_ + r] = w[idx];
    }
}
__global__ void transpose_wout(const float* __restrict__ w) {
    int idx = blockIdx.x * 256 + threadIdx.x;
    if (idx < C_ * C_) {
        int c = idx / C_, k = idx % C_;
        g_woutT[k * C_ + c] = w[idx];
    }
}

// ---------------- QKV projection (round-1 form) ----------------
__global__ __launch_bounds__(256) void qkv_gemm(const float* __restrict__ x) {
    __shared__ float As[16][64];
    __shared__ float Bs[16][128];

    int tid = threadIdx.x;
    int m0 = blockIdx.y * 64;
    int r0 = blockIdx.x * 128;
    int n  = m0 / S_;
    int s0 = m0 % S_;
    int ty = tid / 16;
    int tx = tid % 16;

    ULL acc[4][4];
    #pragma unroll
    for (int i = 0; i < 4; i++)
        #pragma unroll
        for (int j = 0; j < 4; j++) acc[i][j] = 0ull;

    for (int k0 = 0; k0 < C_; k0 += 16) {
        __syncthreads();
        {
            int m4 = tid % 16;
            int kk = tid / 16;
            const float* src = x + (size_t)n * C_ * S_ + (size_t)(k0 + kk) * S_ + s0 + m4 * 4;
            *(float4*)&As[kk][m4 * 4] = *(const float4*)src;
        }
        {
            int r4 = tid % 32;
            int kk = tid / 32;
            #pragma unroll
            for (int p = 0; p < 2; p++) {
                const float* src = g_wqkvT + (size_t)(k0 + kk + p * 8) * C3_ + r0 + r4 * 4;
                *(float4*)&Bs[kk + p * 8][r4 * 4] = *(const float4*)src;
            }
        }
        __syncthreads();

        #pragma unroll
        for (int k = 0; k < 16; k++) {
            float4 a4 = *(const float4*)&As[k][ty * 4];
            ULL ad0 = pack2(a4.x, a4.x), ad1 = pack2(a4.y, a4.y);
            ULL ad2 = pack2(a4.z, a4.z), ad3 = pack2(a4.w, a4.w);
            const ULL* brow = (const ULL*)&Bs[k][tx * 8];
            ULL b0 = brow[0], b1 = brow[1], b2 = brow[2], b3 = brow[3];
            acc[0][0] = fma2(ad0, b0, acc[0][0]); acc[0][1] = fma2(ad0, b1, acc[0][1]);
            acc[0][2] = fma2(ad0, b2, acc[0][2]); acc[0][3] = fma2(ad0, b3, acc[0][3]);
            acc[1][0] = fma2(ad1, b0, acc[1][0]); acc[1][1] = fma2(ad1, b1, acc[1][1]);
            acc[1][2] = fma2(ad1, b2, acc[1][2]); acc[1][3] = fma2(ad1, b3, acc[1][3]);
            acc[2][0] = fma2(ad2, b0, acc[2][0]); acc[2][1] = fma2(ad2, b1, acc[2][1]);
            acc[2][2] = fma2(ad2, b2, acc[2][2]); acc[2][3] = fma2(ad2, b3, acc[2][3]);
            acc[3][0] = fma2(ad3, b0, acc[3][0]); acc[3][1] = fma2(ad3, b1, acc[3][1]);
            acc[3][2] = fma2(ad3, b2, acc[3][2]); acc[3][3] = fma2(ad3, b3, acc[3][3]);
        }
    }

    const float scale = 0.125f;
    #pragma unroll
    for (int mi = 0; mi < 4; mi++) {
        int s = s0 + ty * 4 + mi;
        #pragma unroll
        for (int rp = 0; rp < 4; rp++) {
            float2 v = unpack2(acc[mi][rp]);
            int rbase = r0 + tx * 8 + rp * 2;
            #pragma unroll
            for (int lane = 0; lane < 2; lane++) {
                int r = rbase + lane;
                int t = r / C_;
                int f = r % C_;
                int h = f / D_;
                int d = f % D_;
                float val = lane ? v.y : v.x;
                float* dst;
                if (t == 0)      { dst = g_q; val *= scale; }
                else if (t == 1) { dst = g_k; }
                else             { dst = g_v; }
                dst[(((size_t)(n * NH_ + h)) * S_ + s) * D_ + d] = val;
            }
        }
    }
}

// ---------------- flash attention (register-tiled) ----------------
// 128 threads, 128 queries/block. ty=lane owns 4 q rows; tx=warp owns a
// k-slice (scores) / d-slice (PV). K/V operands are uniform LDS.64 broadcasts;
// Q/P operands are one conflict-free LDS.128 per step serving 4 rows.
#define QPAD 132
#define KPAD 34
#define ATT_SMEM ((64*QPAD + 64*KPAD + 32*64 + 32*QPAD) * 4)

__global__ __launch_bounds__(128) void attn_kernel() {
    extern __shared__ float sm[];
    float* QsT = sm;                       // [64][132]  Q transposed
    float* KsT = QsT + 64 * QPAD;          // [64][34]   K transposed
    float* Vs  = KsT + 64 * KPAD;          // [32][64]
    float* ScT = Vs  + 32 * 64;            // [32][132]  scores transposed

    int nh  = blockIdx.y;
    int tid = threadIdx.x;
    int ty  = tid & 31;       // lane
    int tx  = tid >> 5;       // warp
    int q0  = blockIdx.x * 128;

    const float* qg = g_q + ((size_t)nh * S_ + q0) * D_;
    const float* kb = g_k + (size_t)nh * S_ * D_;
    const float* vb = g_v + (size_t)nh * S_ * D_;

    // load Q block, transposed into smem
    #pragma unroll
    for (int it = 0; it < 16; it++) {
        int idx = it * 128 + tid;       // 0..2047
        int q   = idx >> 4;
        int d4  = idx & 15;
        float4 v = *(const float4*)(qg + q * D_ + d4 * 4);
        QsT[(d4 * 4 + 0) * QPAD + q] = v.x;
        QsT[(d4 * 4 + 1) * QPAD + q] = v.y;
        QsT[(d4 * 4 + 2) * QPAD + q] = v.z;
        QsT[(d4 * 4 + 3) * QPAD + q] = v.w;
    }

    ULL o2[4][8];
    #pragma unroll
    for (int i = 0; i < 4; i++)
        #pragma unroll
        for (int j = 0; j < 8; j++) o2[i][j] = 0ull;
    float m[4] = {-1e30f, -1e30f, -1e30f, -1e30f};
    float l[4] = {0.f, 0.f, 0.f, 0.f};

    // register prefetch of tile 0 (K and V, 4 float4 each per thread)
    float4 pk[4], pv[4];
    #pragma unroll
    for (int it = 0; it < 4; it++) {
        int idx = it * 128 + tid;       // 0..511
        int kk  = idx >> 4;
        int d4  = idx & 15;
        pk[it] = *(const float4*)(kb + (size_t)kk * D_ + d4 * 4);
        pv[it] = *(const float4*)(vb + (size_t)kk * D_ + d4 * 4);
    }

    for (int kt = 0; kt < 32; kt++) {
        __syncthreads();   // prior tile's compute done
        // store prefetched K (transposed) and V
        #pragma unroll
        for (int it = 0; it < 4; it++) {
            int idx = it * 128 + tid;
            int kk  = idx >> 4;
            int d4  = idx & 15;
            KsT[(d4 * 4 + 0) * KPAD + kk] = pk[it].x;
            KsT[(d4 * 4 + 1) * KPAD + kk] = pk[it].y;
            KsT[(d4 * 4 + 2) * KPAD + kk] = pk[it].z;
            KsT[(d4 * 4 + 3) * KPAD + kk] = pk[it].w;
            *(float4*)&Vs[kk * 64 + d4 * 4] = pv[it];
        }
        __syncthreads();
        // prefetch next tile
        if (kt + 1 < 32) {
            const float* kn = kb + (size_t)(kt + 1) * 32 * D_;
            const float* vn = vb + (size_t)(kt + 1) * 32 * D_;
            #pragma unroll
            for (int it = 0; it < 4; it++) {
                int idx = it * 128 + tid;
                int kk  = idx >> 4;
                int d4  = idx & 15;
                pk[it] = *(const float4*)(kn + (size_t)kk * D_ + d4 * 4);
                pv[it] = *(const float4*)(vn + (size_t)kk * D_ + d4 * 4);
            }
        }

        // ---- scores: 4q x 8k per thread, acc packed over k-pairs ----
        ULL acc[4][4];
        #pragma unroll
        for (int i = 0; i < 4; i++)
            #pragma unroll
            for (int j = 0; j < 4; j++) acc[i][j] = 0ull;

        #pragma unroll 8
        for (int d = 0; d < 64; d++) {
            float4 qv = *(const float4*)&QsT[d * QPAD + 4 * ty];   // LDS.128
            ULL qa0 = pack2(qv.x, qv.x);
            ULL qa1 = pack2(qv.y, qv.y);
            ULL qa2 = pack2(qv.z, qv.z);
            ULL qa3 = pack2(qv.w, qv.w);
            const float* kr = &KsT[d * KPAD + 8 * tx];
            ULL k0 = *(const ULL*)(kr + 0);    // broadcast LDS.64
            ULL k1 = *(const ULL*)(kr + 2);
            ULL k2 = *(const ULL*)(kr + 4);
            ULL k3 = *(const ULL*)(kr + 6);
            acc[0][0] = fma2(qa0, k0, acc[0][0]); acc[0][1] = fma2(qa0, k1, acc[0][1]);
            acc[0][2] = fma2(qa0, k2, acc[0][2]); acc[0][3] = fma2(qa0, k3, acc[0][3]);
            acc[1][0] = fma2(qa1, k0, acc[1][0]); acc[1][1] = fma2(qa1, k1, acc[1][1]);
            acc[1][2] = fma2(qa1, k2, acc[1][2]); acc[1][3] = fma2(qa1, k3, acc[1][3]);
            acc[2][0] = fma2(qa2, k0, acc[2][0]); acc[2][1] = fma2(qa2, k1, acc[2][1]);
            acc[2][2] = fma2(qa2, k2, acc[2][2]); acc[2][3] = fma2(qa2, k3, acc[2][3]);
            acc[3][0] = fma2(qa3, k0, acc[3][0]); acc[3][1] = fma2(qa3, k1, acc[3][1]);
            acc[3][2] = fma2(qa3, k2, acc[3][2]); acc[3][3] = fma2(qa3, k3, acc[3][3]);
        }

        // write scores transposed: ScT[k][q], conflict-free STS.128
        #pragma unroll
        for (int jj = 0; jj < 4; jj++) {
            float2 a0 = unpack2(acc[0][jj]);
            float2 a1 = unpack2(acc[1][jj]);
            float2 a2 = unpack2(acc[2][jj]);
            float2 a3 = unpack2(acc[3][jj]);
            int kcol = 8 * tx + 2 * jj;
            *(float4*)&ScT[kcol * QPAD + 4 * ty]       = make_float4(a0.x, a1.x, a2.x, a3.x);
            *(float4*)&ScT[(kcol + 1) * QPAD + 4 * ty] = make_float4(a0.y, a1.y, a2.y, a3.y);
        }
        __syncthreads();

        // ---- per-row max over this tile ----
        float tmax0 = -1e30f, tmax1 = -1e30f, tmax2 = -1e30f, tmax3 = -1e30f;
        #pragma unroll 8
        for (int k = 0; k < 32; k++) {
            float4 s = *(const float4*)&ScT[k * QPAD + 4 * ty];
            tmax0 = fmaxf(tmax0, s.x);
            tmax1 = fmaxf(tmax1, s.y);
            tmax2 = fmaxf(tmax2, s.z);
            tmax3 = fmaxf(tmax3, s.w);
        }
        float tm[4] = {tmax0, tmax1, tmax2, tmax3};
        #pragma unroll
        for (int i = 0; i < 4; i++) {
            if (tm[i] > m[i]) {
                float corr = __expf(m[i] - tm[i]);
                l[i] *= corr;
                m[i] = tm[i];
                ULL cd = pack2(corr, corr);
                #pragma unroll
                for (int j = 0; j < 8; j++) o2[i][j] = mul2(o2[i][j], cd);
            }
        }

        // ---- PV: 4q x 16d per thread ----
        #pragma unroll 4
        for (int k = 0; k < 32; k++) {
            float4 s = *(const float4*)&ScT[k * QPAD + 4 * ty];   // LDS.128
            float p0 = __expf(s.x - m[0]);
            float p1 = __expf(s.y - m[1]);
            float p2 = __expf(s.z - m[2]);
            float p3 = __expf(s.w - m[3]);
            l[0] += p0; l[1] += p1; l[2] += p2; l[3] += p3;
            ULL pd0 = pack2(p0, p0), pd1 = pack2(p1, p1);
            ULL pd2 = pack2(p2, p2), pd3 = pack2(p3, p3);
            const float* vr = &Vs[k * 64 + 16 * tx];
            ULL v0 = *(const ULL*)(vr + 0);   // broadcast LDS.64
            ULL v1 = *(const ULL*)(vr + 2);
            ULL v2 = *(const ULL*)(vr + 4);
            ULL v3 = *(const ULL*)(vr + 6);
            ULL v4 = *(const ULL*)(vr + 8);
            ULL v5 = *(const ULL*)(vr + 10);
            ULL v6 = *(const ULL*)(vr + 12);
            ULL v7 = *(const ULL*)(vr + 14);
            o2[0][0] = fma2(pd0, v0, o2[0][0]); o2[0][1] = fma2(pd0, v1, o2[0][1]);
            o2[0][2] = fma2(pd0, v2, o2[0][2]); o2[0][3] = fma2(pd0, v3, o2[0][3]);
            o2[0][4] = fma2(pd0, v4, o2[0][4]); o2[0][5] = fma2(pd0, v5, o2[0][5]);
            o2[0][6] = fma2(pd0, v6, o2[0][6]); o2[0][7] = fma2(pd0, v7, o2[0][7]);
            o2[1][0] = fma2(pd1, v0, o2[1][0]); o2[1][1] = fma2(pd1, v1, o2[1][1]);
            o2[1][2] = fma2(pd1, v2, o2[1][2]); o2[1][3] = fma2(pd1, v3, o2[1][3]);
            o2[1][4] = fma2(pd1, v4, o2[1][4]); o2[1][5] = fma2(pd1, v5, o2[1][5]);
            o2[1][6] = fma2(pd1, v6, o2[1][6]); o2[1][7] = fma2(pd1, v7, o2[1][7]);
            o2[2][0] = fma2(pd2, v0, o2[2][0]); o2[2][1] = fma2(pd2, v1, o2[2][1]);
            o2[2][2] = fma2(pd2, v2, o2[2][2]); o2[2][3] = fma2(pd2, v3, o2[2][3]);
            o2[2][4] = fma2(pd2, v4, o2[2][4]); o2[2][5] = fma2(pd2, v5, o2[2][5]);
            o2[2][6] = fma2(pd2, v6, o2[2][6]); o2[2][7] = fma2(pd2, v7, o2[2][7]);
            o2[3][0] = fma2(pd3, v0, o2[3][0]); o2[3][1] = fma2(pd3, v1, o2[3][1]);
            o2[3][2] = fma2(pd3, v2, o2[3][2]); o2[3][3] = fma2(pd3, v3, o2[3][3]);
            o2[3][4] = fma2(pd3, v4, o2[3][4]); o2[3][5] = fma2(pd3, v5, o2[3][5]);
            o2[3][6] = fma2(pd3, v6, o2[3][6]); o2[3][7] = fma2(pd3, v7, o2[3][7]);
        }
    }

    // epilogue: thread owns rows q0+4ty+i, cols h*64 + 16tx .. +15
    int n = nh / NH_, h = nh % NH_;
    #pragma unroll
    for (int i = 0; i < 4; i++) {
        float inv = 1.0f / l[i];
        ULL iv = pack2(inv, inv);
        int s = q0 + 4 * ty + i;
        float* dst = g_ao + ((size_t)(n * S_ + s)) * C_ + h * D_ + 16 * tx;
        #pragma unroll
        for (int mm = 0; mm < 4; mm++) {
            float2 lo = unpack2(mul2(o2[i][2 * mm], iv));
            float2 hi = unpack2(mul2(o2[i][2 * mm + 1], iv));
            *(float4*)(dst + 4 * mm) = make_float4(lo.x, lo.y, hi.x, hi.y);
        }
    }
}

// ---------------- output projection (round-1 form) ----------------
__global__ __launch_bounds__(256) void proj_gemm(const float* __restrict__ bias,
                                                 float* __restrict__ out) {
    __shared__ float As[64][16];
    __shared__ float Bs[16][128];

    int tid = threadIdx.x;
    int m0 = blockIdx.y * 64;
    int c0 = blockIdx.x * 128;
    int n  = m0 / S_;
    int s0 = m0 % S_;
    int ty = tid / 16;
    int tx = tid % 16;

    ULL acc[4][4];
    #pragma unroll
    for (int i = 0; i < 4; i++)
        #pragma unroll
        for (int j = 0; j < 4; j++) acc[i][j] = 0ull;

    for (int k0 = 0; k0 < C_; k0 += 16) {
        __syncthreads();
        {
            int k4 = tid % 4;
            int mm = tid / 4;
            const float* src = g_ao + (size_t)(m0 + mm) * C_ + k0 + k4 * 4;
            *(float4*)&As[mm][k4 * 4] = *(const float4*)src;
        }
        {
            int r4 = tid % 32;
            int kk = tid / 32;
            #pragma unroll
            for (int p = 0; p < 2; p++) {
                const float* src = g_woutT + (size_t)(k0 + kk + p * 8) * C_ + c0 + r4 * 4;
                *(float4*)&Bs[kk + p * 8][r4 * 4] = *(const float4*)src;
            }
        }
        __syncthreads();

        #pragma unroll
        for (int k = 0; k < 16; k++) {
            float a0 = As[ty * 4 + 0][k];
            float a1 = As[ty * 4 + 1][k];
            float a2 = As[ty * 4 + 2][k];
            float a3 = As[ty * 4 + 3][k];
            ULL ad0 = pack2(a0, a0), ad1 = pack2(a1, a1);
            ULL ad2 = pack2(a2, a2), ad3 = pack2(a3, a3);
            const ULL* brow = (const ULL*)&Bs[k][tx * 8];
            ULL b0 = brow[0], b1 = brow[1], b2 = brow[2], b3 = brow[3];
            acc[0][0] = fma2(ad0, b0, acc[0][0]); acc[0][1] = fma2(ad0, b1, acc[0][1]);
            acc[0][2] = fma2(ad0, b2, acc[0][2]); acc[0][3] = fma2(ad0, b3, acc[0][3]);
            acc[1][0] = fma2(ad1, b0, acc[1][0]); acc[1][1] = fma2(ad1, b1, acc[1][1]);
            acc[1][2] = fma2(ad1, b2, acc[1][2]); acc[1][3] = fma2(ad1, b3, acc[1][3]);
            acc[2][0] = fma2(ad2, b0, acc[2][0]); acc[2][1] = fma2(ad2, b1, acc[2][1]);
            acc[2][2] = fma2(ad2, b2, acc[2][2]); acc[2][3] = fma2(ad2, b3, acc[2][3]);
            acc[3][0] = fma2(ad3, b0, acc[3][0]); acc[3][1] = fma2(ad3, b1, acc[3][1]);
            acc[3][2] = fma2(ad3, b2, acc[3][2]); acc[3][3] = fma2(ad3, b3, acc[3][3]);
        }
    }

    #pragma unroll
    for (int mi = 0; mi < 4; mi++) {
        int s = s0 + ty * 4 + mi;
        #pragma unroll
        for (int rp = 0; rp < 4; rp++) {
            float2 v = unpack2(acc[mi][rp]);
            int c = c0 + tx * 8 + rp * 2;
            out[(size_t)n * C_ * S_ + (size_t)c * S_ + s]       = v.x + bias[c];
            out[(size_t)n * C_ * S_ + (size_t)(c + 1) * S_ + s] = v.y + bias[c + 1];
        }
    }
}

// ---------------- launch ----------------
extern "C" void kernel_launch(void* const* d_in, const int* in_sizes, int n_in,
                              void* d_out, int out_size) {
    const float* x     = (const float*)d_in[0];
    const float* w_qkv = (const float*)d_in[1];
    const float* w_out = (const float*)d_in[2];
    const float* b_out = (const float*)d_in[3];
    float* out = (float*)d_out;

    cudaFuncSetAttribute(attn_kernel, cudaFuncAttributeMaxDynamicSharedMemorySize, ATT_SMEM);

    transpose_wqkv<<<(C3_ * C_ + 255) / 256, 256>>>(w_qkv);
    transpose_wout<<<(C_ * C_ + 255) / 256, 256>>>(w_out);

    qkv_gemm<<<dim3(C3_ / 128, M_ / 64), 256>>>(x);

    attn_kernel<<<dim3(S_ / 128, N_ * NH_), 128, ATT_SMEM>>>();

    proj_gemm<<<dim3(C_ / 128, M_ / 64), 256>>>(b_out, out);
}

// round 5
// speedup vs baseline: 1.5520x; 1.2742x over previous
#include <cuda_runtime.h>
#include <cstdint>

typedef unsigned long long ULL;

#define N_   16
#define C_   384
#define S_   1024
#define NH_  6
#define D_   64
#define C3_  1152
#define M_   (N_*S_)

// ---------------- scratch (device globals; no allocation) ----------------
__device__ float g_tok_hi[M_*C_],  g_tok_lo[M_*C_];    // tokens, tf32 split, [m][k]
__device__ float g_wqkv_hi[C3_*C_], g_wqkv_lo[C3_*C_]; // [r][k]
__device__ float g_wout_hi[C_*C_],  g_wout_lo[C_*C_];  // [c][k]
__device__ float g_q[N_*NH_*S_*D_];                    // pre-scaled
__device__ float g_k[N_*NH_*S_*D_];
__device__ float g_v[N_*NH_*S_*D_];
__device__ float g_ao[M_*C_];                          // attention out fp32 [m][c]
__device__ float g_ao_hi[M_*C_], g_ao_lo[M_*C_];

// ---------------- helpers ----------------
__device__ __forceinline__ ULL pack2(float lo, float hi) {
    ULL r; asm("mov.b64 %0, {%1, %2};" : "=l"(r) : "f"(lo), "f"(hi)); return r;
}
__device__ __forceinline__ float2 unpack2(ULL a) {
    float2 f; asm("mov.b64 {%0, %1}, %2;" : "=f"(f.x), "=f"(f.y) : "l"(a)); return f;
}
__device__ __forceinline__ ULL fma2(ULL a, ULL b, ULL c) {
    ULL d; asm("fma.rn.f32x2 %0, %1, %2, %3;" : "=l"(d) : "l"(a), "l"(b), "l"(c)); return d;
}
__device__ __forceinline__ ULL mul2(ULL a, ULL b) {
    ULL d; asm("mul.rn.f32x2 %0, %1, %2;" : "=l"(d) : "l"(a), "l"(b)); return d;
}
__device__ __forceinline__ float tf32_rna(float x) {
    uint32_t r; asm("cvt.rna.tf32.f32 %0, %1;" : "=r"(r) : "f"(x));
    return __uint_as_float(r);
}
__device__ __forceinline__ uint32_t smem_u32(const void* p) {
    uint32_t a;
    asm("{ .reg .u64 t; cvta.to.shared.u64 t, %1; cvt.u32.u64 %0, t; }" : "=r"(a) : "l"(p));
    return a;
}
__device__ __forceinline__ uint32_t lds32(uint32_t a) {
    uint32_t v; asm volatile("ld.shared.b32 %0, [%1];" : "=r"(v) : "r"(a)); return v;
}
__device__ __forceinline__ void cp16(uint32_t saddr, const float* g) {
    size_t ga = __cvta_generic_to_global((const void*)g);
    asm volatile("cp.async.cg.shared.global [%0], [%1], 16;" :: "r"(saddr), "l"(ga) : "memory");
}
#define CP_COMMIT() asm volatile("cp.async.commit_group;" ::: "memory")
#define CP_WAIT(n)  asm volatile("cp.async.wait_group %0;" :: "n"(n) : "memory")

#define MMA_TF32(d, a, b0, b1)                                              \
    asm volatile("mma.sync.aligned.m16n8k8.row.col.f32.tf32.tf32.f32 "      \
        "{%0,%1,%2,%3}, {%4,%5,%6,%7}, {%8,%9}, {%0,%1,%2,%3};"             \
        : "+f"((d)[0]), "+f"((d)[1]), "+f"((d)[2]), "+f"((d)[3])            \
        : "r"((a)[0]), "r"((a)[1]), "r"((a)[2]), "r"((a)[3]),               \
          "r"(b0), "r"(b1))

// ---------------- input prep ----------------
// x[n][k][s] -> tokens[m][k] with tf32 hi/lo split
__global__ void transpose_x(const float* __restrict__ x) {
    __shared__ float t[32][33];
    int n = blockIdx.z, k0 = blockIdx.y * 32, s0 = blockIdx.x * 32;
    int tx = threadIdx.x, ty = threadIdx.y;
    const float* src = x + ((size_t)n * C_ + k0) * S_ + s0;
    #pragma unroll
    for (int j = 0; j < 4; j++)
        t[ty + 8 * j][tx] = src[(size_t)(ty + 8 * j) * S_ + tx];
    __syncthreads();
    size_t base = ((size_t)n * S_ + s0) * C_ + k0;
    #pragma unroll
    for (int j = 0; j < 4; j++) {
        float a = t[tx][ty + 8 * j];
        float h = tf32_rna(a);
        size_t o = base + (size_t)(ty + 8 * j) * C_ + tx;
        g_tok_hi[o] = h;
        g_tok_lo[o] = tf32_rna(a - h);
    }
}

__global__ void split_wqkv(const float* __restrict__ w) {
    int i = blockIdx.x * 256 + threadIdx.x;
    if (i < C3_ * C_) {
        float a = w[i], h = tf32_rna(a);
        g_wqkv_hi[i] = h; g_wqkv_lo[i] = tf32_rna(a - h);
    }
}
__global__ void split_wout(const float* __restrict__ w) {
    int i = blockIdx.x * 256 + threadIdx.x;
    if (i < C_ * C_) {
        float a = w[i], h = tf32_rna(a);
        g_wout_hi[i] = h; g_wout_lo[i] = tf32_rna(a - h);
    }
}
__global__ void split_ao() {
    int i = blockIdx.x * 256 + threadIdx.x;   // one float4 per thread
    float4 a = *((const float4*)g_ao + i);
    float4 h, l;
    h.x = tf32_rna(a.x); l.x = tf32_rna(a.x - h.x);
    h.y = tf32_rna(a.y); l.y = tf32_rna(a.y - h.y);
    h.z = tf32_rna(a.z); l.z = tf32_rna(a.z - h.z);
    h.w = tf32_rna(a.w); l.w = tf32_rna(a.w - h.w);
    *((float4*)g_ao_hi + i) = h;
    *((float4*)g_ao_lo + i) = l;
}

// ---------------- 3xTF32 mma.sync GEMM ----------------
// mode 0: D[m][r] = tok[m][k] . wqkv[r][k]   grid(9,128)  -> q/k/v scatter
// mode 1: D[c][m] = wout[c][k] . ao[m][k]    grid(128,3)  -> out[n][c][s] + bias
#define KCH 16
#define STRD 20                              // padded row stride (u32) -> 80B, conflict-free
#define HALF_B (128*STRD*4)                  // 10240
#define STAGE_B (4*HALF_B)                   // 40960
#define GEMM_SMEM (2*STAGE_B)                // 81920

__global__ __launch_bounds__(256) void mma_gemm(
    int mode, const float* __restrict__ bias, float* __restrict__ out)
{
    extern __shared__ __align__(16) char smem[];
    uint32_t sbase = smem_u32(smem);
    int tid = threadIdx.x;
    int lane = tid & 31, w = tid >> 5;
    int wm = w & 3, wn = w >> 1 >> 1;        // wn = w>>2
    int by = blockIdx.y, bx = blockIdx.x;

    const float *Ahp, *Alp, *Bhp, *Blp;
    if (mode == 0) { Ahp = g_tok_hi;  Alp = g_tok_lo;  Bhp = g_wqkv_hi; Blp = g_wqkv_lo; }
    else           { Ahp = g_wout_hi; Alp = g_wout_lo; Bhp = g_ao_hi;   Blp = g_ao_lo; }
    const float* Ah = Ahp + (size_t)by * 128 * C_;
    const float* Al = Alp + (size_t)by * 128 * C_;
    const float* Bh = Bhp + (size_t)bx * 128 * C_;
    const float* Bl = Blp + (size_t)bx * 128 * C_;

    float acc[2][8][4];
    #pragma unroll
    for (int i = 0; i < 2; i++)
        #pragma unroll
        for (int j = 0; j < 8; j++)
            #pragma unroll
            for (int q = 0; q < 4; q++) acc[i][j][q] = 0.0f;

    // ---- cp.async tile loader ----
    auto issue = [&](int c, int st) {
        uint32_t s0 = sbase + st * STAGE_B;
        #pragma unroll
        for (int i = 0; i < 2; i++) {
            int idx = i * 256 + tid;           // 0..511
            int row = idx >> 2, seg = idx & 3; // seg: 16B unit (4 floats)
            size_t go = (size_t)row * C_ + c * KCH + seg * 4;
            uint32_t so = row * 80 + seg * 16;
            cp16(s0 + so,              Ah + go);
            cp16(s0 + HALF_B + so,     Al + go);
            cp16(s0 + 2 * HALF_B + so, Bh + go);
            cp16(s0 + 3 * HALF_B + so, Bl + go);
        }
        CP_COMMIT();
    };

    issue(0, 0);

    const int NCH = C_ / KCH;   // 24
    for (int c = 0; c < NCH; c++) {
        int st = c & 1;
        if (c + 1 < NCH) { issue(c + 1, st ^ 1); CP_WAIT(1); }
        else             { CP_WAIT(0); }
        __syncthreads();

        uint32_t sA  = sbase + st * STAGE_B;
        uint32_t sAl = sA + HALF_B;
        uint32_t sB  = sA + 2 * HALF_B;
        uint32_t sBl = sA + 3 * HALF_B;

        #pragma unroll
        for (int sub = 0; sub < 2; sub++) {
            int kb = sub * 8 + (lane & 3);             // k column index
            uint32_t ahi[2][4], alo[2][4];
            #pragma unroll
            for (int mi = 0; mi < 2; mi++) {
                int r0 = wm * 32 + mi * 16 + (lane >> 2);
                uint32_t o0 = (uint32_t)r0 * 80 + (uint32_t)kb * 4;
                uint32_t o1 = o0 + 8 * 80;
                ahi[mi][0] = lds32(sA + o0);  ahi[mi][1] = lds32(sA + o1);
                ahi[mi][2] = lds32(sA + o0 + 16); ahi[mi][3] = lds32(sA + o1 + 16);
                alo[mi][0] = lds32(sAl + o0); alo[mi][1] = lds32(sAl + o1);
                alo[mi][2] = lds32(sAl + o0 + 16); alo[mi][3] = lds32(sAl + o1 + 16);
            }
            #pragma unroll
            for (int ni = 0; ni < 8; ni++) {
                int n0 = wn * 64 + ni * 8 + (lane >> 2);
                uint32_t bo = (uint32_t)n0 * 80 + (uint32_t)kb * 4;
                uint32_t bh0 = lds32(sB + bo),  bh1 = lds32(sB + bo + 16);
                uint32_t bl0 = lds32(sBl + bo), bl1 = lds32(sBl + bo + 16);
                #pragma unroll
                for (int mi = 0; mi < 2; mi++) {
                    MMA_TF32(acc[mi][ni], ahi[mi], bh0, bh1);
                    MMA_TF32(acc[mi][ni], ahi[mi], bl0, bl1);
                    MMA_TF32(acc[mi][ni], alo[mi], bh0, bh1);
                }
            }
        }
        __syncthreads();
    }

    // ---- epilogue ----
    int row = lane >> 2, colp = (lane & 3) * 2;
    if (mode == 0) {
        #pragma unroll
        for (int ni = 0; ni < 8; ni++) {
            int rf = bx * 128 + wn * 64 + ni * 8 + colp;
            int t = rf / C_;
            int rem = rf - t * C_;
            int h = rem >> 6, d = rem & 63;
            float* bp = (t == 0) ? g_q : (t == 1 ? g_k : g_v);
            float sc = (t == 0) ? 0.125f : 1.0f;
            #pragma unroll
            for (int mi = 0; mi < 2; mi++) {
                int mb = by * 128 + wm * 32 + mi * 16 + row;
                #pragma unroll
                for (int rr = 0; rr < 2; rr++) {
                    int m = mb + rr * 8;
                    int n = m >> 10, s = m & 1023;
                    float2 v = make_float2(acc[mi][ni][rr * 2] * sc,
                                           acc[mi][ni][rr * 2 + 1] * sc);
                    *(float2*)(bp + ((size_t)(n * NH_ + h) * S_ + s) * D_ + d) = v;
                }
            }
        }
    } else {
        #pragma unroll
        for (int ni = 0; ni < 8; ni++) {
            int m = bx * 128 + wn * 64 + ni * 8 + colp;
            int n = m >> 10, s = m & 1023;
            #pragma unroll
            for (int mi = 0; mi < 2; mi++) {
                int cb = by * 128 + wm * 32 + mi * 16 + row;
                #pragma unroll
                for (int rr = 0; rr < 2; rr++) {
                    int cc = cb + rr * 8;
                    float bb = bias[cc];
                    float2 v = make_float2(acc[mi][ni][rr * 2] + bb,
                                           acc[mi][ni][rr * 2 + 1] + bb);
                    *(float2*)(out + ((size_t)n * C_ + cc) * S_ + s) = v;
                }
            }
        }
    }
}

// ---------------- flash attention (round-3, unchanged, 770us) ----------------
#define QPAD 132
#define KPAD 34
#define ATT_SMEM ((64*QPAD + 64*KPAD + 32*64 + 32*QPAD) * 4)

__global__ __launch_bounds__(128) void attn_kernel() {
    extern __shared__ float smf[];
    float* QsT = smf;
    float* KsT = QsT + 64 * QPAD;
    float* Vs  = KsT + 64 * KPAD;
    float* ScT = Vs  + 32 * 64;

    int nh  = blockIdx.y;
    int tid = threadIdx.x;
    int ty  = tid & 31;
    int tx  = tid >> 5;
    int q0  = blockIdx.x * 128;

    const float* qg = g_q + ((size_t)nh * S_ + q0) * D_;
    const float* kb = g_k + (size_t)nh * S_ * D_;
    const float* vb = g_v + (size_t)nh * S_ * D_;

    #pragma unroll
    for (int it = 0; it < 16; it++) {
        int idx = it * 128 + tid;
        int q   = idx >> 4;
        int d4  = idx & 15;
        float4 v = *(const float4*)(qg + q * D_ + d4 * 4);
        QsT[(d4 * 4 + 0) * QPAD + q] = v.x;
        QsT[(d4 * 4 + 1) * QPAD + q] = v.y;
        QsT[(d4 * 4 + 2) * QPAD + q] = v.z;
        QsT[(d4 * 4 + 3) * QPAD + q] = v.w;
    }

    ULL o2[4][8];
    #pragma unroll
    for (int i = 0; i < 4; i++)
        #pragma unroll
        for (int j = 0; j < 8; j++) o2[i][j] = 0ull;
    float m[4] = {-1e30f, -1e30f, -1e30f, -1e30f};
    float l[4] = {0.f, 0.f, 0.f, 0.f};

    float4 pk[4], pv[4];
    #pragma unroll
    for (int it = 0; it < 4; it++) {
        int idx = it * 128 + tid;
        int kk  = idx >> 4;
        int d4  = idx & 15;
        pk[it] = *(const float4*)(kb + (size_t)kk * D_ + d4 * 4);
        pv[it] = *(const float4*)(vb + (size_t)kk * D_ + d4 * 4);
    }

    for (int kt = 0; kt < 32; kt++) {
        __syncthreads();
        #pragma unroll
        for (int it = 0; it < 4; it++) {
            int idx = it * 128 + tid;
            int kk  = idx >> 4;
            int d4  = idx & 15;
            KsT[(d4 * 4 + 0) * KPAD + kk] = pk[it].x;
            KsT[(d4 * 4 + 1) * KPAD + kk] = pk[it].y;
            KsT[(d4 * 4 + 2) * KPAD + kk] = pk[it].z;
            KsT[(d4 * 4 + 3) * KPAD + kk] = pk[it].w;
            *(float4*)&Vs[kk * 64 + d4 * 4] = pv[it];
        }
        __syncthreads();
        if (kt + 1 < 32) {
            const float* kn = kb + (size_t)(kt + 1) * 32 * D_;
            const float* vn = vb + (size_t)(kt + 1) * 32 * D_;
            #pragma unroll
            for (int it = 0; it < 4; it++) {
                int idx = it * 128 + tid;
                int kk  = idx >> 4;
                int d4  = idx & 15;
                pk[it] = *(const float4*)(kn + (size_t)kk * D_ + d4 * 4);
                pv[it] = *(const float4*)(vn + (size_t)kk * D_ + d4 * 4);
            }
        }

        ULL acc[4][4];
        #pragma unroll
        for (int i = 0; i < 4; i++)
            #pragma unroll
            for (int j = 0; j < 4; j++) acc[i][j] = 0ull;

        #pragma unroll 8
        for (int d = 0; d < 64; d++) {
            float4 qv = *(const float4*)&QsT[d * QPAD + 4 * ty];
            ULL qa0 = pack2(qv.x, qv.x);
            ULL qa1 = pack2(qv.y, qv.y);
            ULL qa2 = pack2(qv.z, qv.z);
            ULL qa3 = pack2(qv.w, qv.w);
            const float* kr = &KsT[d * KPAD + 8 * tx];
            ULL k0 = *(const ULL*)(kr + 0);
            ULL k1 = *(const ULL*)(kr + 2);
            ULL k2 = *(const ULL*)(kr + 4);
            ULL k3 = *(const ULL*)(kr + 6);
            acc[0][0] = fma2(qa0, k0, acc[0][0]); acc[0][1] = fma2(qa0, k1, acc[0][1]);
            acc[0][2] = fma2(qa0, k2, acc[0][2]); acc[0][3] = fma2(qa0, k3, acc[0][3]);
            acc[1][0] = fma2(qa1, k0, acc[1][0]); acc[1][1] = fma2(qa1, k1, acc[1][1]);
            acc[1][2] = fma2(qa1, k2, acc[1][2]); acc[1][3] = fma2(qa1, k3, acc[1][3]);
            acc[2][0] = fma2(qa2, k0, acc[2][0]); acc[2][1] = fma2(qa2, k1, acc[2][1]);
            acc[2][2] = fma2(qa2, k2, acc[2][2]); acc[2][3] = fma2(qa2, k3, acc[2][3]);
            acc[3][0] = fma2(qa3, k0, acc[3][0]); acc[3][1] = fma2(qa3, k1, acc[3][1]);
            acc[3][2] = fma2(qa3, k2, acc[3][2]); acc[3][3] = fma2(qa3, k3, acc[3][3]);
        }

        #pragma unroll
        for (int jj = 0; jj < 4; jj++) {
            float2 a0 = unpack2(acc[0][jj]);
            float2 a1 = unpack2(acc[1][jj]);
            float2 a2 = unpack2(acc[2][jj]);
            float2 a3 = unpack2(acc[3][jj]);
            int kcol = 8 * tx + 2 * jj;
            *(float4*)&ScT[kcol * QPAD + 4 * ty]       = make_float4(a0.x, a1.x, a2.x, a3.x);
            *(float4*)&ScT[(kcol + 1) * QPAD + 4 * ty] = make_float4(a0.y, a1.y, a2.y, a3.y);
        }
        __syncthreads();

        float tmax0 = -1e30f, tmax1 = -1e30f, tmax2 = -1e30f, tmax3 = -1e30f;
        #pragma unroll 8
        for (int k = 0; k < 32; k++) {
            float4 s = *(const float4*)&ScT[k * QPAD + 4 * ty];
            tmax0 = fmaxf(tmax0, s.x);
            tmax1 = fmaxf(tmax1, s.y);
            tmax2 = fmaxf(tmax2, s.z);
            tmax3 = fmaxf(tmax3, s.w);
        }
        float tm[4] = {tmax0, tmax1, tmax2, tmax3};
        #pragma unroll
        for (int i = 0; i < 4; i++) {
            if (tm[i] > m[i]) {
                float corr = __expf(m[i] - tm[i]);
                l[i] *= corr;
                m[i] = tm[i];
                ULL cd = pack2(corr, corr);
                #pragma unroll
                for (int j = 0; j < 8; j++) o2[i][j] = mul2(o2[i][j], cd);
            }
        }

        #pragma unroll 4
        for (int k = 0; k < 32; k++) {
            float4 s = *(const float4*)&ScT[k * QPAD + 4 * ty];
            float p0 = __expf(s.x - m[0]);
            float p1 = __expf(s.y - m[1]);
            float p2 = __expf(s.z - m[2]);
            float p3 = __expf(s.w - m[3]);
            l[0] += p0; l[1] += p1; l[2] += p2; l[3] += p3;
            ULL pd0 = pack2(p0, p0), pd1 = pack2(p1, p1);
            ULL pd2 = pack2(p2, p2), pd3 = pack2(p3, p3);
            const float* vr = &Vs[k * 64 + 16 * tx];
            ULL v0 = *(const ULL*)(vr + 0);
            ULL v1 = *(const ULL*)(vr + 2);
            ULL v2 = *(const ULL*)(vr + 4);
            ULL v3 = *(const ULL*)(vr + 6);
            ULL v4 = *(const ULL*)(vr + 8);
            ULL v5 = *(const ULL*)(vr + 10);
            ULL v6 = *(const ULL*)(vr + 12);
            ULL v7 = *(const ULL*)(vr + 14);
            o2[0][0] = fma2(pd0, v0, o2[0][0]); o2[0][1] = fma2(pd0, v1, o2[0][1]);
            o2[0][2] = fma2(pd0, v2, o2[0][2]); o2[0][3] = fma2(pd0, v3, o2[0][3]);
            o2[0][4] = fma2(pd0, v4, o2[0][4]); o2[0][5] = fma2(pd0, v5, o2[0][5]);
            o2[0][6] = fma2(pd0, v6, o2[0][6]); o2[0][7] = fma2(pd0, v7, o2[0][7]);
            o2[1][0] = fma2(pd1, v0, o2[1][0]); o2[1][1] = fma2(pd1, v1, o2[1][1]);
            o2[1][2] = fma2(pd1, v2, o2[1][2]); o2[1][3] = fma2(pd1, v3, o2[1][3]);
            o2[1][4] = fma2(pd1, v4, o2[1][4]); o2[1][5] = fma2(pd1, v5, o2[1][5]);
            o2[1][6] = fma2(pd1, v6, o2[1][6]); o2[1][7] = fma2(pd1, v7, o2[1][7]);
            o2[2][0] = fma2(pd2, v0, o2[2][0]); o2[2][1] = fma2(pd2, v1, o2[2][1]);
            o2[2][2] = fma2(pd2, v2, o2[2][2]); o2[2][3] = fma2(pd2, v3, o2[2][3]);
            o2[2][4] = fma2(pd2, v4, o2[2][4]); o2[2][5] = fma2(pd2, v5, o2[2][5]);
            o2[2][6] = fma2(pd2, v6, o2[2][6]); o2[2][7] = fma2(pd2, v7, o2[2][7]);
            o2[3][0] = fma2(pd3, v0, o2[3][0]); o2[3][1] = fma2(pd3, v1, o2[3][1]);
            o2[3][2] = fma2(pd3, v2, o2[3][2]); o2[3][3] = fma2(pd3, v3, o2[3][3]);
            o2[3][4] = fma2(pd3, v4, o2[3][4]); o2[3][5] = fma2(pd3, v5, o2[3][5]);
            o2[3][6] = fma2(pd3, v6, o2[3][6]); o2[3][7] = fma2(pd3, v7, o2[3][7]);
        }
    }

    int n = nh / NH_, h = nh % NH_;
    #pragma unroll
    for (int i = 0; i < 4; i++) {
        float inv = 1.0f / l[i];
        ULL iv = pack2(inv, inv);
        int s = q0 + 4 * ty + i;
        float* dst = g_ao + ((size_t)(n * S_ + s)) * C_ + h * D_ + 16 * tx;
        #pragma unroll
        for (int mm = 0; mm < 4; mm++) {
            float2 lo = unpack2(mul2(o2[i][2 * mm], iv));
            float2 hi = unpack2(mul2(o2[i][2 * mm + 1], iv));
            *(float4*)(dst + 4 * mm) = make_float4(lo.x, lo.y, hi.x, hi.y);
        }
    }
}

// ---------------- launch ----------------
extern "C" void kernel_launch(void* const* d_in, const int* in_sizes, int n_in,
                              void* d_out, int out_size) {
    const float* x     = (const float*)d_in[0];
    const float* w_qkv = (const float*)d_in[1];
    const float* w_out = (const float*)d_in[2];
    const float* b_out = (const float*)d_in[3];
    float* out = (float*)d_out;

    cudaFuncSetAttribute(attn_kernel, cudaFuncAttributeMaxDynamicSharedMemorySize, ATT_SMEM);
    cudaFuncSetAttribute(mma_gemm, cudaFuncAttributeMaxDynamicSharedMemorySize, GEMM_SMEM);

    transpose_x<<<dim3(S_ / 32, C_ / 32, N_), dim3(32, 8)>>>(x);
    split_wqkv<<<(C3_ * C_ + 255) / 256, 256>>>(w_qkv);
    split_wout<<<(C_ * C_ + 255) / 256, 256>>>(w_out);

    // qkv: bx = feature tiles (9), by = token tiles (128)
    mma_gemm<<<dim3(C3_ / 128, M_ / 128), 256, GEMM_SMEM>>>(0, nullptr, nullptr);

    attn_kernel<<<dim3(S_ / 128, N_ * NH_), 128, ATT_SMEM>>>();

    split_ao<<<(M_ * C_ / 4) / 256, 256>>>();

    // proj: bx = token tiles (128), by = c tiles (3)
    mma_gemm<<<dim3(M_ / 128, C_ / 128), 256, GEMM_SMEM>>>(1, b_out, out);
}

// round 6
// speedup vs baseline: 1.5542x; 1.0014x over previous
#include <cuda_runtime.h>
#include <cstdint>

typedef unsigned long long ULL;

#define N_   16
#define C_   384
#define S_   1024
#define NH_  6
#define D_   64
#define C3_  1152
#define M_   (N_*S_)

// ---------------- scratch (device globals; no allocation) ----------------
__device__ float g_tok_hi[M_*C_],  g_tok_lo[M_*C_];    // tokens, tf32 split, [m][k]
__device__ float g_wqkv_hi[C3_*C_], g_wqkv_lo[C3_*C_]; // [r][k]
__device__ float g_wout_hi[C_*C_],  g_wout_lo[C_*C_];  // [c][k]
__device__ float g_q[N_*NH_*S_*D_];                    // pre-scaled
__device__ float g_k[N_*NH_*S_*D_];
__device__ float g_v[N_*NH_*S_*D_];
__device__ float g_ao[M_*C_];                          // attention out fp32 [m][c]
__device__ float g_ao_hi[M_*C_], g_ao_lo[M_*C_];

// ---------------- helpers ----------------
__device__ __forceinline__ ULL pack2(float lo, float hi) {
    ULL r; asm("mov.b64 %0, {%1, %2};" : "=l"(r) : "f"(lo), "f"(hi)); return r;
}
__device__ __forceinline__ float2 unpack2(ULL a) {
    float2 f; asm("mov.b64 {%0, %1}, %2;" : "=f"(f.x), "=f"(f.y) : "l"(a)); return f;
}
__device__ __forceinline__ ULL fma2(ULL a, ULL b, ULL c) {
    ULL d; asm("fma.rn.f32x2 %0, %1, %2, %3;" : "=l"(d) : "l"(a), "l"(b), "l"(c)); return d;
}
__device__ __forceinline__ ULL mul2(ULL a, ULL b) {
    ULL d; asm("mul.rn.f32x2 %0, %1, %2;" : "=l"(d) : "l"(a), "l"(b)); return d;
}
__device__ __forceinline__ float tf32_rna(float x) {
    uint32_t r; asm("cvt.rna.tf32.f32 %0, %1;" : "=r"(r) : "f"(x));
    return __uint_as_float(r);
}
__device__ __forceinline__ uint32_t smem_u32(const void* p) {
    uint32_t a;
    asm("{ .reg .u64 t; cvta.to.shared.u64 t, %1; cvt.u32.u64 %0, t; }" : "=r"(a) : "l"(p));
    return a;
}
__device__ __forceinline__ uint32_t lds32(uint32_t a) {
    uint32_t v; asm volatile("ld.shared.b32 %0, [%1];" : "=r"(v) : "r"(a)); return v;
}
__device__ __forceinline__ void cp16(uint32_t saddr, const float* g) {
    size_t ga = __cvta_generic_to_global((const void*)g);
    asm volatile("cp.async.cg.shared.global [%0], [%1], 16;" :: "r"(saddr), "l"(ga) : "memory");
}
#define CP_COMMIT() asm volatile("cp.async.commit_group;" ::: "memory")
#define CP_WAIT(n)  asm volatile("cp.async.wait_group %0;" :: "n"(n) : "memory")

#define MMA_TF32(d, a, b0, b1)                                              \
    asm volatile("mma.sync.aligned.m16n8k8.row.col.f32.tf32.tf32.f32 "      \
        "{%0,%1,%2,%3}, {%4,%5,%6,%7}, {%8,%9}, {%0,%1,%2,%3};"             \
        : "+f"((d)[0]), "+f"((d)[1]), "+f"((d)[2]), "+f"((d)[3])            \
        : "r"((a)[0]), "r"((a)[1]), "r"((a)[2]), "r"((a)[3]),               \
          "r"(b0), "r"(b1))

// ---------------- input prep ----------------
// x[n][k][s] -> tokens[m][k] with tf32 hi/lo split
__global__ void transpose_x(const float* __restrict__ x) {
    __shared__ float t[32][33];
    int n = blockIdx.z, k0 = blockIdx.y * 32, s0 = blockIdx.x * 32;
    int tx = threadIdx.x, ty = threadIdx.y;
    const float* src = x + ((size_t)n * C_ + k0) * S_ + s0;
    #pragma unroll
    for (int j = 0; j < 4; j++)
        t[ty + 8 * j][tx] = src[(size_t)(ty + 8 * j) * S_ + tx];
    __syncthreads();
    size_t base = ((size_t)n * S_ + s0) * C_ + k0;
    #pragma unroll
    for (int j = 0; j < 4; j++) {
        float a = t[tx][ty + 8 * j];
        float h = tf32_rna(a);
        size_t o = base + (size_t)(ty + 8 * j) * C_ + tx;
        g_tok_hi[o] = h;
        g_tok_lo[o] = tf32_rna(a - h);
    }
}

__global__ void split_wqkv(const float* __restrict__ w) {
    int i = blockIdx.x * 256 + threadIdx.x;
    if (i < C3_ * C_) {
        float a = w[i], h = tf32_rna(a);
        g_wqkv_hi[i] = h; g_wqkv_lo[i] = tf32_rna(a - h);
    }
}
__global__ void split_wout(const float* __restrict__ w) {
    int i = blockIdx.x * 256 + threadIdx.x;
    if (i < C_ * C_) {
        float a = w[i], h = tf32_rna(a);
        g_wout_hi[i] = h; g_wout_lo[i] = tf32_rna(a - h);
    }
}
__global__ void split_ao() {
    int i = blockIdx.x * 256 + threadIdx.x;   // one float4 per thread
    float4 a = *((const float4*)g_ao + i);
    float4 h, l;
    h.x = tf32_rna(a.x); l.x = tf32_rna(a.x - h.x);
    h.y = tf32_rna(a.y); l.y = tf32_rna(a.y - h.y);
    h.z = tf32_rna(a.z); l.z = tf32_rna(a.z - h.z);
    h.w = tf32_rna(a.w); l.w = tf32_rna(a.w - h.w);
    *((float4*)g_ao_hi + i) = h;
    *((float4*)g_ao_lo + i) = l;
}

// ---------------- 3xTF32 mma.sync GEMM ----------------
// mode 0: D[m][r] = tok[m][k] . wqkv[r][k]   grid(9,128)  -> q/k/v scatter
// mode 1: D[c][m] = wout[c][k] . ao[m][k]    grid(128,3)  -> out[n][c][s] + bias
#define KCH 16
#define STRD 20                              // padded row stride (u32) -> 80B, conflict-free
#define HALF_B (128*STRD*4)                  // 10240
#define STAGE_B (4*HALF_B)                   // 40960
#define GEMM_SMEM (2*STAGE_B)                // 81920

__global__ __launch_bounds__(256) void mma_gemm(
    int mode, const float* __restrict__ bias, float* __restrict__ out)
{
    extern __shared__ __align__(16) char smem[];
    uint32_t sbase = smem_u32(smem);
    int tid = threadIdx.x;
    int lane = tid & 31, w = tid >> 5;
    int wm = w & 3, wn = w >> 1 >> 1;        // wn = w>>2
    int by = blockIdx.y, bx = blockIdx.x;

    const float *Ahp, *Alp, *Bhp, *Blp;
    if (mode == 0) { Ahp = g_tok_hi;  Alp = g_tok_lo;  Bhp = g_wqkv_hi; Blp = g_wqkv_lo; }
    else           { Ahp = g_wout_hi; Alp = g_wout_lo; Bhp = g_ao_hi;   Blp = g_ao_lo; }
    const float* Ah = Ahp + (size_t)by * 128 * C_;
    const float* Al = Alp + (size_t)by * 128 * C_;
    const float* Bh = Bhp + (size_t)bx * 128 * C_;
    const float* Bl = Blp + (size_t)bx * 128 * C_;

    float acc[2][8][4];
    #pragma unroll
    for (int i = 0; i < 2; i++)
        #pragma unroll
        for (int j = 0; j < 8; j++)
            #pragma unroll
            for (int q = 0; q < 4; q++) acc[i][j][q] = 0.0f;

    // ---- cp.async tile loader ----
    auto issue = [&](int c, int st) {
        uint32_t s0 = sbase + st * STAGE_B;
        #pragma unroll
        for (int i = 0; i < 2; i++) {
            int idx = i * 256 + tid;           // 0..511
            int row = idx >> 2, seg = idx & 3; // seg: 16B unit (4 floats)
            size_t go = (size_t)row * C_ + c * KCH + seg * 4;
            uint32_t so = row * 80 + seg * 16;
            cp16(s0 + so,              Ah + go);
            cp16(s0 + HALF_B + so,     Al + go);
            cp16(s0 + 2 * HALF_B + so, Bh + go);
            cp16(s0 + 3 * HALF_B + so, Bl + go);
        }
        CP_COMMIT();
    };

    issue(0, 0);

    const int NCH = C_ / KCH;   // 24
    for (int c = 0; c < NCH; c++) {
        int st = c & 1;
        if (c + 1 < NCH) { issue(c + 1, st ^ 1); CP_WAIT(1); }
        else             { CP_WAIT(0); }
        __syncthreads();

        uint32_t sA  = sbase + st * STAGE_B;
        uint32_t sAl = sA + HALF_B;
        uint32_t sB  = sA + 2 * HALF_B;
        uint32_t sBl = sA + 3 * HALF_B;

        #pragma unroll
        for (int sub = 0; sub < 2; sub++) {
            int kb = sub * 8 + (lane & 3);             // k column index
            uint32_t ahi[2][4], alo[2][4];
            #pragma unroll
            for (int mi = 0; mi < 2; mi++) {
                int r0 = wm * 32 + mi * 16 + (lane >> 2);
                uint32_t o0 = (uint32_t)r0 * 80 + (uint32_t)kb * 4;
                uint32_t o1 = o0 + 8 * 80;
                ahi[mi][0] = lds32(sA + o0);  ahi[mi][1] = lds32(sA + o1);
                ahi[mi][2] = lds32(sA + o0 + 16); ahi[mi][3] = lds32(sA + o1 + 16);
                alo[mi][0] = lds32(sAl + o0); alo[mi][1] = lds32(sAl + o1);
                alo[mi][2] = lds32(sAl + o0 + 16); alo[mi][3] = lds32(sAl + o1 + 16);
            }
            #pragma unroll
            for (int ni = 0; ni < 8; ni++) {
                int n0 = wn * 64 + ni * 8 + (lane >> 2);
                uint32_t bo = (uint32_t)n0 * 80 + (uint32_t)kb * 4;
                uint32_t bh0 = lds32(sB + bo),  bh1 = lds32(sB + bo + 16);
                uint32_t bl0 = lds32(sBl + bo), bl1 = lds32(sBl + bo + 16);
                #pragma unroll
                for (int mi = 0; mi < 2; mi++) {
                    MMA_TF32(acc[mi][ni], ahi[mi], bh0, bh1);
                    MMA_TF32(acc[mi][ni], ahi[mi], bl0, bl1);
                    MMA_TF32(acc[mi][ni], alo[mi], bh0, bh1);
                }
            }
        }
        __syncthreads();
    }

    // ---- epilogue ----
    int row = lane >> 2, colp = (lane & 3) * 2;
    if (mode == 0) {
        #pragma unroll
        for (int ni = 0; ni < 8; ni++) {
            int rf = bx * 128 + wn * 64 + ni * 8 + colp;
            int t = rf / C_;
            int rem = rf - t * C_;
            int h = rem >> 6, d = rem & 63;
            float* bp = (t == 0) ? g_q : (t == 1 ? g_k : g_v);
            float sc = (t == 0) ? 0.125f : 1.0f;
            #pragma unroll
            for (int mi = 0; mi < 2; mi++) {
                int mb = by * 128 + wm * 32 + mi * 16 + row;
                #pragma unroll
                for (int rr = 0; rr < 2; rr++) {
                    int m = mb + rr * 8;
                    int n = m >> 10, s = m & 1023;
                    float2 v = make_float2(acc[mi][ni][rr * 2] * sc,
                                           acc[mi][ni][rr * 2 + 1] * sc);
                    *(float2*)(bp + ((size_t)(n * NH_ + h) * S_ + s) * D_ + d) = v;
                }
            }
        }
    } else {
        #pragma unroll
        for (int ni = 0; ni < 8; ni++) {
            int m = bx * 128 + wn * 64 + ni * 8 + colp;
            int n = m >> 10, s = m & 1023;
            #pragma unroll
            for (int mi = 0; mi < 2; mi++) {
                int cb = by * 128 + wm * 32 + mi * 16 + row;
                #pragma unroll
                for (int rr = 0; rr < 2; rr++) {
                    int cc = cb + rr * 8;
                    float bb = bias[cc];
                    float2 v = make_float2(acc[mi][ni][rr * 2] + bb,
                                           acc[mi][ni][rr * 2 + 1] + bb);
                    *(float2*)(out + ((size_t)n * C_ + cc) * S_ + s) = v;
                }
            }
        }
    }
}

// ---------------- flash attention (round-3, unchanged, 770us) ----------------
#define QPAD 132
#define KPAD 34
#define ATT_SMEM ((64*QPAD + 64*KPAD + 32*64 + 32*QPAD) * 4)

__global__ __launch_bounds__(128) void attn_kernel() {
    extern __shared__ float smf[];
    float* QsT = smf;
    float* KsT = QsT + 64 * QPAD;
    float* Vs  = KsT + 64 * KPAD;
    float* ScT = Vs  + 32 * 64;

    int nh  = blockIdx.y;
    int tid = threadIdx.x;
    int ty  = tid & 31;
    int tx  = tid >> 5;
    int q0  = blockIdx.x * 128;

    const float* qg = g_q + ((size_t)nh * S_ + q0) * D_;
    const float* kb = g_k + (size_t)nh * S_ * D_;
    const float* vb = g_v + (size_t)nh * S_ * D_;

    #pragma unroll
    for (int it = 0; it < 16; it++) {
        int idx = it * 128 + tid;
        int q   = idx >> 4;
        int d4  = idx & 15;
        float4 v = *(const float4*)(qg + q * D_ + d4 * 4);
        QsT[(d4 * 4 + 0) * QPAD + q] = v.x;
        QsT[(d4 * 4 + 1) * QPAD + q] = v.y;
        QsT[(d4 * 4 + 2) * QPAD + q] = v.z;
        QsT[(d4 * 4 + 3) * QPAD + q] = v.w;
    }

    ULL o2[4][8];
    #pragma unroll
    for (int i = 0; i < 4; i++)
        #pragma unroll
        for (int j = 0; j < 8; j++) o2[i][j] = 0ull;
    float m[4] = {-1e30f, -1e30f, -1e30f, -1e30f};
    float l[4] = {0.f, 0.f, 0.f, 0.f};

    float4 pk[4], pv[4];
    #pragma unroll
    for (int it = 0; it < 4; it++) {
        int idx = it * 128 + tid;
        int kk  = idx >> 4;
        int d4  = idx & 15;
        pk[it] = *(const float4*)(kb + (size_t)kk * D_ + d4 * 4);
        pv[it] = *(const float4*)(vb + (size_t)kk * D_ + d4 * 4);
    }

    for (int kt = 0; kt < 32; kt++) {
        __syncthreads();
        #pragma unroll
        for (int it = 0; it < 4; it++) {
            int idx = it * 128 + tid;
            int kk  = idx >> 4;
            int d4  = idx & 15;
            KsT[(d4 * 4 + 0) * KPAD + kk] = pk[it].x;
            KsT[(d4 * 4 + 1) * KPAD + kk] = pk[it].y;
            KsT[(d4 * 4 + 2) * KPAD + kk] = pk[it].z;
            KsT[(d4 * 4 + 3) * KPAD + kk] = pk[it].w;
            *(float4*)&Vs[kk * 64 + d4 * 4] = pv[it];
        }
        __syncthreads();
        if (kt + 1 < 32) {
            const float* kn = kb + (size_t)(kt + 1) * 32 * D_;
            const float* vn = vb + (size_t)(kt + 1) * 32 * D_;
            #pragma unroll
            for (int it = 0; it < 4; it++) {
                int idx = it * 128 + tid;
                int kk  = idx >> 4;
                int d4  = idx & 15;
                pk[it] = *(const float4*)(kn + (size_t)kk * D_ + d4 * 4);
                pv[it] = *(const float4*)(vn + (size_t)kk * D_ + d4 * 4);
            }
        }

        ULL acc[4][4];
        #pragma unroll
        for (int i = 0; i < 4; i++)
            #pragma unroll
            for (int j = 0; j < 4; j++) acc[i][j] = 0ull;

        #pragma unroll 8
        for (int d = 0; d < 64; d++) {
            float4 qv = *(const float4*)&QsT[d * QPAD + 4 * ty];
            ULL qa0 = pack2(qv.x, qv.x);
            ULL qa1 = pack2(qv.y, qv.y);
            ULL qa2 = pack2(qv.z, qv.z);
            ULL qa3 = pack2(qv.w, qv.w);
            const float* kr = &KsT[d * KPAD + 8 * tx];
            ULL k0 = *(const ULL*)(kr + 0);
            ULL k1 = *(const ULL*)(kr + 2);
            ULL k2 = *(const ULL*)(kr + 4);
            ULL k3 = *(const ULL*)(kr + 6);
            acc[0][0] = fma2(qa0, k0, acc[0][0]); acc[0][1] = fma2(qa0, k1, acc[0][1]);
            acc[0][2] = fma2(qa0, k2, acc[0][2]); acc[0][3] = fma2(qa0, k3, acc[0][3]);
            acc[1][0] = fma2(qa1, k0, acc[1][0]); acc[1][1] = fma2(qa1, k1, acc[1][1]);
            acc[1][2] = fma2(qa1, k2, acc[1][2]); acc[1][3] = fma2(qa1, k3, acc[1][3]);
            acc[2][0] = fma2(qa2, k0, acc[2][0]); acc[2][1] = fma2(qa2, k1, acc[2][1]);
            acc[2][2] = fma2(qa2, k2, acc[2][2]); acc[2][3] = fma2(qa2, k3, acc[2][3]);
            acc[3][0] = fma2(qa3, k0, acc[3][0]); acc[3][1] = fma2(qa3, k1, acc[3][1]);
            acc[3][2] = fma2(qa3, k2, acc[3][2]); acc[3][3] = fma2(qa3, k3, acc[3][3]);
        }

        #pragma unroll
        for (int jj = 0; jj < 4; jj++) {
            float2 a0 = unpack2(acc[0][jj]);
            float2 a1 = unpack2(acc[1][jj]);
            float2 a2 = unpack2(acc[2][jj]);
            float2 a3 = unpack2(acc[3][jj]);
            int kcol = 8 * tx + 2 * jj;
            *(float4*)&ScT[kcol * QPAD + 4 * ty]       = make_float4(a0.x, a1.x, a2.x, a3.x);
            *(float4*)&ScT[(kcol + 1) * QPAD + 4 * ty] = make_float4(a0.y, a1.y, a2.y, a3.y);
        }
        __syncthreads();

        float tmax0 = -1e30f, tmax1 = -1e30f, tmax2 = -1e30f, tmax3 = -1e30f;
        #pragma unroll 8
        for (int k = 0; k < 32; k++) {
            float4 s = *(const float4*)&ScT[k * QPAD + 4 * ty];
            tmax0 = fmaxf(tmax0, s.x);
            tmax1 = fmaxf(tmax1, s.y);
            tmax2 = fmaxf(tmax2, s.z);
            tmax3 = fmaxf(tmax3, s.w);
        }
        float tm[4] = {tmax0, tmax1, tmax2, tmax3};
        #pragma unroll
        for (int i = 0; i < 4; i++) {
            if (tm[i] > m[i]) {
                float corr = __expf(m[i] - tm[i]);
                l[i] *= corr;
                m[i] = tm[i];
                ULL cd = pack2(corr, corr);
                #pragma unroll
                for (int j = 0; j < 8; j++) o2[i][j] = mul2(o2[i][j], cd);
            }
        }

        #pragma unroll 4
        for (int k = 0; k < 32; k++) {
            float4 s = *(const float4*)&ScT[k * QPAD + 4 * ty];
            float p0 = __expf(s.x - m[0]);
            float p1 = __expf(s.y - m[1]);
            float p2 = __expf(s.z - m[2]);
            float p3 = __expf(s.w - m[3]);
            l[0] += p0; l[1] += p1; l[2] += p2; l[3] += p3;
            ULL pd0 = pack2(p0, p0), pd1 = pack2(p1, p1);
            ULL pd2 = pack2(p2, p2), pd3 = pack2(p3, p3);
            const float* vr = &Vs[k * 64 + 16 * tx];
            ULL v0 = *(const ULL*)(vr + 0);
            ULL v1 = *(const ULL*)(vr + 2);
            ULL v2 = *(const ULL*)(vr + 4);
            ULL v3 = *(const ULL*)(vr + 6);
            ULL v4 = *(const ULL*)(vr + 8);
            ULL v5 = *(const ULL*)(vr + 10);
            ULL v6 = *(const ULL*)(vr + 12);
            ULL v7 = *(const ULL*)(vr + 14);
            o2[0][0] = fma2(pd0, v0, o2[0][0]); o2[0][1] = fma2(pd0, v1, o2[0][1]);
            o2[0][2] = fma2(pd0, v2, o2[0][2]); o2[0][3] = fma2(pd0, v3, o2[0][3]);
            o2[0][4] = fma2(pd0, v4, o2[0][4]); o2[0][5] = fma2(pd0, v5, o2[0][5]);
            o2[0][6] = fma2(pd0, v6, o2[0][6]); o2[0][7] = fma2(pd0, v7, o2[0][7]);
            o2[1][0] = fma2(pd1, v0, o2[1][0]); o2[1][1] = fma2(pd1, v1, o2[1][1]);
            o2[1][2] = fma2(pd1, v2, o2[1][2]); o2[1][3] = fma2(pd1, v3, o2[1][3]);
            o2[1][4] = fma2(pd1, v4, o2[1][4]); o2[1][5] = fma2(pd1, v5, o2[1][5]);
            o2[1][6] = fma2(pd1, v6, o2[1][6]); o2[1][7] = fma2(pd1, v7, o2[1][7]);
            o2[2][0] = fma2(pd2, v0, o2[2][0]); o2[2][1] = fma2(pd2, v1, o2[2][1]);
            o2[2][2] = fma2(pd2, v2, o2[2][2]); o2[2][3] = fma2(pd2, v3, o2[2][3]);
            o2[2][4] = fma2(pd2, v4, o2[2][4]); o2[2][5] = fma2(pd2, v5, o2[2][5]);
            o2[2][6] = fma2(pd2, v6, o2[2][6]); o2[2][7] = fma2(pd2, v7, o2[2][7]);
            o2[3][0] = fma2(pd3, v0, o2[3][0]); o2[3][1] = fma2(pd3, v1, o2[3][1]);
            o2[3][2] = fma2(pd3, v2, o2[3][2]); o2[3][3] = fma2(pd3, v3, o2[3][3]);
            o2[3][4] = fma2(pd3, v4, o2[3][4]); o2[3][5] = fma2(pd3, v5, o2[3][5]);
            o2[3][6] = fma2(pd3, v6, o2[3][6]); o2[3][7] = fma2(pd3, v7, o2[3][7]);
        }
    }

    int n = nh / NH_, h = nh % NH_;
    #pragma unroll
    for (int i = 0; i < 4; i++) {
        float inv = 1.0f / l[i];
        ULL iv = pack2(inv, inv);
        int s = q0 + 4 * ty + i;
        float* dst = g_ao + ((size_t)(n * S_ + s)) * C_ + h * D_ + 16 * tx;
        #pragma unroll
        for (int mm = 0; mm < 4; mm++) {
            float2 lo = unpack2(mul2(o2[i][2 * mm], iv));
            float2 hi = unpack2(mul2(o2[i][2 * mm + 1], iv));
            *(float4*)(dst + 4 * mm) = make_float4(lo.x, lo.y, hi.x, hi.y);
        }
    }
}

// ---------------- launch ----------------
extern "C" void kernel_launch(void* const* d_in, const int* in_sizes, int n_in,
                              void* d_out, int out_size) {
    const float* x     = (const float*)d_in[0];
    const float* w_qkv = (const float*)d_in[1];
    const float* w_out = (const float*)d_in[2];
    const float* b_out = (const float*)d_in[3];
    float* out = (float*)d_out;

    cudaFuncSetAttribute(attn_kernel, cudaFuncAttributeMaxDynamicSharedMemorySize, ATT_SMEM);
    cudaFuncSetAttribute(mma_gemm, cudaFuncAttributeMaxDynamicSharedMemorySize, GEMM_SMEM);

    transpose_x<<<dim3(S_ / 32, C_ / 32, N_), dim3(32, 8)>>>(x);
    split_wqkv<<<(C3_ * C_ + 255) / 256, 256>>>(w_qkv);
    split_wout<<<(C_ * C_ + 255) / 256, 256>>>(w_out);

    // qkv: bx = feature tiles (9), by = token tiles (128)
    mma_gemm<<<dim3(C3_ / 128, M_ / 128), 256, GEMM_SMEM>>>(0, nullptr, nullptr);

    attn_kernel<<<dim3(S_ / 128, N_ * NH_), 128, ATT_SMEM>>>();

    split_ao<<<(M_ * C_ / 4) / 256, 256>>>();

    // proj: bx = token tiles (128), by = c tiles (3)
    mma_gemm<<<dim3(M_ / 128, C_ / 128), 256, GEMM_SMEM>>>(1, b_out, out);
}

// round 8
// speedup vs baseline: 2.0324x; 1.3077x over previous
#include <cuda_runtime.h>
#include <cstdint>

#define N_   16
#define C_   384
#define S_   1024
#define NH_  6
#define D_   64
#define C3_  1152
#define M_   (N_*S_)

__device__ float g_tok_hi[M_*C_],  g_tok_lo[M_*C_];
__device__ float g_wqkv_hi[C3_*C_], g_wqkv_lo[C3_*C_];
__device__ float g_wout_hi[C_*C_],  g_wout_lo[C_*C_];
__device__ float g_q[N_*NH_*S_*D_];                   // fp32, 0.125 folded
__device__ float g_kh[N_*NH_*S_*D_], g_kl[N_*NH_*S_*D_];
__device__ float g_vh[N_*NH_*D_*S_], g_vl[N_*NH_*D_*S_];   // V^T
__device__ float g_ao[M_*C_];
__device__ float g_ao_hi[M_*C_], g_ao_lo[M_*C_];

__device__ __forceinline__ float tf32_rna(float x) {
    uint32_t r; asm("cvt.rna.tf32.f32 %0, %1;" : "=r"(r) : "f"(x));
    return __uint_as_float(r);
}
__device__ __forceinline__ uint32_t smem_u32(const void* p) {
    uint32_t a;
    asm("{ .reg .u64 t; cvta.to.shared.u64 t, %1; cvt.u32.u64 %0, t; }" : "=r"(a) : "l"(p));
    return a;
}
__device__ __forceinline__ uint32_t lds32(uint32_t a) {
    uint32_t v; asm volatile("ld.shared.b32 %0, [%1];" : "=r"(v) : "r"(a)); return v;
}
__device__ __forceinline__ void cp16(uint32_t saddr, const float* g) {
    size_t ga = __cvta_generic_to_global((const void*)g);
    asm volatile("cp.async.cg.shared.global [%0], [%1], 16;" :: "r"(saddr), "l"(ga) : "memory");
}
#define CP_COMMIT() asm volatile("cp.async.commit_group;" ::: "memory")
#define CP_WAIT0()  asm volatile("cp.async.wait_group 0;" ::: "memory")
#define CP_WAIT1()  asm volatile("cp.async.wait_group 1;" ::: "memory")
#define CP_WAIT2()  asm volatile("cp.async.wait_group 2;" ::: "memory")
#define FU(x) __float_as_uint(x)

#define MMA_TF32(d, a, b0, b1)                                              \
    asm volatile("mma.sync.aligned.m16n8k8.row.col.f32.tf32.tf32.f32 "      \
        "{%0,%1,%2,%3}, {%4,%5,%6,%7}, {%8,%9}, {%0,%1,%2,%3};"             \
        : "+f"((d)[0]), "+f"((d)[1]), "+f"((d)[2]), "+f"((d)[3])            \
        : "r"((a)[0]), "r"((a)[1]), "r"((a)[2]), "r"((a)[3]),               \
          "r"(b0), "r"(b1))

// ---------------- input prep ----------------
__global__ void transpose_x(const float* __restrict__ x) {
    __shared__ float t[32][33];
    int n = blockIdx.z, k0 = blockIdx.y * 32, s0 = blockIdx.x * 32;
    int tx = threadIdx.x, ty = threadIdx.y;
    const float* src = x + ((size_t)n * C_ + k0) * S_ + s0;
    #pragma unroll
    for (int j = 0; j < 4; j++)
        t[ty + 8 * j][tx] = src[(size_t)(ty + 8 * j) * S_ + tx];
    __syncthreads();
    size_t base = ((size_t)n * S_ + s0) * C_ + k0;
    #pragma unroll
    for (int j = 0; j < 4; j++) {
        float a = t[tx][ty + 8 * j];
        float h = tf32_rna(a);
        size_t o = base + (size_t)(ty + 8 * j) * C_ + tx;
        g_tok_hi[o] = h;
        g_tok_lo[o] = tf32_rna(a - h);
    }
}
__global__ void split_wqkv(const float* __restrict__ w) {
    int i = blockIdx.x * 256 + threadIdx.x;
    if (i < C3_ * C_) { float a = w[i], h = tf32_rna(a); g_wqkv_hi[i] = h; g_wqkv_lo[i] = tf32_rna(a - h); }
}
__global__ void split_wout(const float* __restrict__ w) {
    int i = blockIdx.x * 256 + threadIdx.x;
    if (i < C_ * C_) { float a = w[i], h = tf32_rna(a); g_wout_hi[i] = h; g_wout_lo[i] = tf32_rna(a - h); }
}
__global__ void split_ao() {
    int i = blockIdx.x * 256 + threadIdx.x;
    float4 a = *((const float4*)g_ao + i);
    float4 h, l;
    h.x = tf32_rna(a.x); l.x = tf32_rna(a.x - h.x);
    h.y = tf32_rna(a.y); l.y = tf32_rna(a.y - h.y);
    h.z = tf32_rna(a.z); l.z = tf32_rna(a.z - h.z);
    h.w = tf32_rna(a.w); l.w = tf32_rna(a.w - h.w);
    *((float4*)g_ao_hi + i) = h;
    *((float4*)g_ao_lo + i) = l;
}

// ---------------- 3xTF32 mma.sync GEMM ----------------
#define KCH 16
#define HALF_B (128*20*4)
#define STAGE_B (4*HALF_B)
#define GEMM_SMEM (2*STAGE_B)

__global__ __launch_bounds__(256) void mma_gemm(
    int mode, const float* __restrict__ bias, float* __restrict__ out)
{
    extern __shared__ __align__(16) char smem[];
    uint32_t sbase = smem_u32(smem);
    int tid = threadIdx.x;
    int lane = tid & 31, w = tid >> 5;
    int wm = w & 3, wn = w >> 2;
    int by = blockIdx.y, bx = blockIdx.x;

    const float *Ahp, *Alp, *Bhp, *Blp;
    if (mode == 0) { Ahp = g_tok_hi;  Alp = g_tok_lo;  Bhp = g_wqkv_hi; Blp = g_wqkv_lo; }
    else           { Ahp = g_wout_hi; Alp = g_wout_lo; Bhp = g_ao_hi;   Blp = g_ao_lo; }
    const float* Ah = Ahp + (size_t)by * 128 * C_;
    const float* Al = Alp + (size_t)by * 128 * C_;
    const float* Bh = Bhp + (size_t)bx * 128 * C_;
    const float* Bl = Blp + (size_t)bx * 128 * C_;

    float acc[2][8][4];
    #pragma unroll
    for (int i = 0; i < 2; i++)
        #pragma unroll
        for (int j = 0; j < 8; j++)
            #pragma unroll
            for (int q = 0; q < 4; q++) acc[i][j][q] = 0.0f;

    auto issue = [&](int c, int st) {
        uint32_t s0 = sbase + st * STAGE_B;
        #pragma unroll
        for (int i = 0; i < 2; i++) {
            int idx = i * 256 + tid;
            int row = idx >> 2, seg = idx & 3;
            size_t go = (size_t)row * C_ + c * KCH + seg * 4;
            uint32_t so = row * 80 + seg * 16;
            cp16(s0 + so,              Ah + go);
            cp16(s0 + HALF_B + so,     Al + go);
            cp16(s0 + 2 * HALF_B + so, Bh + go);
            cp16(s0 + 3 * HALF_B + so, Bl + go);
        }
        CP_COMMIT();
    };

    issue(0, 0);
    const int NCH = C_ / KCH;
    for (int c = 0; c < NCH; c++) {
        int st = c & 1;
        if (c + 1 < NCH) { issue(c + 1, st ^ 1); CP_WAIT1(); }
        else             { CP_WAIT0(); }
        __syncthreads();

        uint32_t sA  = sbase + st * STAGE_B;
        uint32_t sAl = sA + HALF_B;
        uint32_t sB  = sA + 2 * HALF_B;
        uint32_t sBl = sA + 3 * HALF_B;

        #pragma unroll
        for (int sub = 0; sub < 2; sub++) {
            int kb = sub * 8 + (lane & 3);
            uint32_t ahi[2][4], alo[2][4];
            #pragma unroll
            for (int mi = 0; mi < 2; mi++) {
                int r0 = wm * 32 + mi * 16 + (lane >> 2);
                uint32_t o0 = (uint32_t)r0 * 80 + (uint32_t)kb * 4;
                uint32_t o1 = o0 + 8 * 80;
                ahi[mi][0] = lds32(sA + o0);  ahi[mi][1] = lds32(sA + o1);
                ahi[mi][2] = lds32(sA + o0 + 16); ahi[mi][3] = lds32(sA + o1 + 16);
                alo[mi][0] = lds32(sAl + o0); alo[mi][1] = lds32(sAl + o1);
                alo[mi][2] = lds32(sAl + o0 + 16); alo[mi][3] = lds32(sAl + o1 + 16);
            }
            #pragma unroll
            for (int ni = 0; ni < 8; ni++) {
                int n0 = wn * 64 + ni * 8 + (lane >> 2);
                uint32_t bo = (uint32_t)n0 * 80 + (uint32_t)kb * 4;
                uint32_t bh0 = lds32(sB + bo),  bh1 = lds32(sB + bo + 16);
                uint32_t bl0 = lds32(sBl + bo), bl1 = lds32(sBl + bo + 16);
                #pragma unroll
                for (int mi = 0; mi < 2; mi++) {
                    MMA_TF32(acc[mi][ni], ahi[mi], bh0, bh1);
                    MMA_TF32(acc[mi][ni], ahi[mi], bl0, bl1);
                    MMA_TF32(acc[mi][ni], alo[mi], bh0, bh1);
                }
            }
        }
        __syncthreads();
    }

    int row = lane >> 2, colp = (lane & 3) * 2;
    if (mode == 0) {
        #pragma unroll
        for (int ni = 0; ni < 8; ni++) {
            int rf = bx * 128 + wn * 64 + ni * 8 + colp;
            int t = rf / C_;
            int rem = rf - t * C_;
            int h = rem >> 6, d = rem & 63;
            #pragma unroll
            for (int mi = 0; mi < 2; mi++) {
                int mb = by * 128 + wm * 32 + mi * 16 + row;
                #pragma unroll
                for (int rr = 0; rr < 2; rr++) {
                    int m = mb + rr * 8;
                    int n = m >> 10, s = m & 1023;
                    int nh = n * NH_ + h;
                    float v0 = acc[mi][ni][rr * 2], v1 = acc[mi][ni][rr * 2 + 1];
                    if (t == 0) {
                        *(float2*)(g_q + ((size_t)nh * S_ + s) * D_ + d) =
                            make_float2(v0 * 0.125f, v1 * 0.125f);
                    } else if (t == 1) {
                        float h0 = tf32_rna(v0), h1 = tf32_rna(v1);
                        size_t off = ((size_t)nh * S_ + s) * D_ + d;
                        *(float2*)(g_kh + off) = make_float2(h0, h1);
                        *(float2*)(g_kl + off) = make_float2(tf32_rna(v0 - h0), tf32_rna(v1 - h1));
                    } else {
                        float h0 = tf32_rna(v0), h1 = tf32_rna(v1);
                        size_t o0 = ((size_t)nh * D_ + d) * S_ + s;
                        g_vh[o0] = h0;      g_vl[o0] = tf32_rna(v0 - h0);
                        g_vh[o0 + S_] = h1; g_vl[o0 + S_] = tf32_rna(v1 - h1);
                    }
                }
            }
        }
    } else {
        #pragma unroll
        for (int ni = 0; ni < 8; ni++) {
            int m = bx * 128 + wn * 64 + ni * 8 + colp;
            int n = m >> 10, s = m & 1023;
            #pragma unroll
            for (int mi = 0; mi < 2; mi++) {
                int cb = by * 128 + wm * 32 + mi * 16 + row;
                #pragma unroll
                for (int rr = 0; rr < 2; rr++) {
                    int cc = cb + rr * 8;
                    float bb = bias[cc];
                    float2 v = make_float2(acc[mi][ni][rr * 2] + bb,
                                           acc[mi][ni][rr * 2 + 1] + bb);
                    *(float2*)(out + ((size_t)n * C_ + cc) * S_ + s) = v;
                }
            }
        }
    }
}

// ---------------- tensor-core flash attention ----------------
// 256 thr; warp w owns q rows [w*16, w*16+16). 64-key tiles, 16 iters.
// QK and PV both 3-pass compensated tf32. P staged in warp-private smem rows.
#define AST 68
#define ATT2_SMEM (43520*4)

__global__ __launch_bounds__(256) void attn_mma() {
    extern __shared__ __align__(16) float sm[];
    float* Pb  = sm;           // [128][68] (Q staging, then P)
    float* KhS = sm + 8704;    // 2 x [64][68]
    float* KlS = sm + 17408;
    float* VhS = sm + 26112;   // V^T: [d][key]
    float* VlS = sm + 34816;

    int tid = threadIdx.x;
    int lane = tid & 31, w = tid >> 5;
    int rq = lane >> 2, kq = lane & 3;
    int nh = blockIdx.y, q0 = blockIdx.x * 128;

    const float* qg  = g_q  + ((size_t)nh * S_ + q0) * D_;
    const float* khg = g_kh + (size_t)nh * S_ * D_;
    const float* klg = g_kl + (size_t)nh * S_ * D_;
    const float* vhg = g_vh + (size_t)nh * D_ * S_;
    const float* vlg = g_vl + (size_t)nh * D_ * S_;

    // group 1: Q -> Pb   (128 rows x 64 floats = 2048 16B-segs)
    #pragma unroll
    for (int i = 0; i < 8; i++) {
        int idx = i * 256 + tid;
        int r = idx >> 4, sg = idx & 15;
        cp16(smem_u32(&Pb[r * AST + sg * 4]), qg + (size_t)r * D_ + sg * 4);
    }
    CP_COMMIT();

    // groups 2,3: K/V tiles 0,1   (each array: 64 rows x 16 segs = 1024 segs)
    #pragma unroll
    for (int t = 0; t < 2; t++) {
        #pragma unroll
        for (int i = 0; i < 4; i++) {
            int idx = i * 256 + tid;
            int row = idx >> 4, sg = idx & 15;
            uint32_t bo = (uint32_t)(t * 4352 + row * AST + sg * 4) * 4;
            cp16(smem_u32(KhS) + bo, khg + (size_t)(t * 64 + row) * D_ + sg * 4);
            cp16(smem_u32(KlS) + bo, klg + (size_t)(t * 64 + row) * D_ + sg * 4);
            cp16(smem_u32(VhS) + bo, vhg + (size_t)row * S_ + t * 64 + sg * 4);
            cp16(smem_u32(VlS) + bo, vlg + (size_t)row * S_ + t * 64 + sg * 4);
        }
        CP_COMMIT();
    }

    CP_WAIT2();
    __syncthreads();

    // Q fragments, hi/lo split in registers (exact)
    uint32_t qah[8][4], qal[8][4];
    {
        const float* q0p = &Pb[(w * 16 + rq) * AST + kq];
        #pragma unroll
        for (int s = 0; s < 8; s++) {
            float f[4];
            f[0] = q0p[s * 8];           f[1] = q0p[8 * AST + s * 8];
            f[2] = q0p[s * 8 + 4];       f[3] = q0p[8 * AST + s * 8 + 4];
            #pragma unroll
            for (int j = 0; j < 4; j++) {
                float h = tf32_rna(f[j]);
                qah[s][j] = FU(h);
                qal[s][j] = FU(tf32_rna(f[j] - h));
            }
        }
    }
    __syncthreads();

    float o[8][4];
    #pragma unroll
    for (int n = 0; n < 8; n++)
        #pragma unroll
        for (int j = 0; j < 4; j++) o[n][j] = 0.0f;
    float m0 = -1e30f, m1 = -1e30f, l0 = 0.0f, l1 = 0.0f;

    for (int kt = 0; kt < 16; kt++) {
        if (kt < 15) { CP_WAIT1(); } else { CP_WAIT0(); }
        __syncthreads();
        int boff = (kt & 1) * 4352;

        // ---- QK^T (3-pass) ----
        float acc[8][4];
        #pragma unroll
        for (int n = 0; n < 8; n++)
            #pragma unroll
            for (int j = 0; j < 4; j++) acc[n][j] = 0.0f;

        #pragma unroll
        for (int s = 0; s < 8; s++) {
            #pragma unroll
            for (int n = 0; n < 8; n++) {
                int bi = boff + (n * 8 + rq) * AST + s * 8 + kq;
                uint32_t bh0 = FU(KhS[bi]), bh1 = FU(KhS[bi + 4]);
                uint32_t bl0 = FU(KlS[bi]), bl1 = FU(KlS[bi + 4]);
                MMA_TF32(acc[n], qah[s], bh0, bh1);
                MMA_TF32(acc[n], qah[s], bl0, bl1);
                MMA_TF32(acc[n], qal[s], bh0, bh1);
            }
        }

        // ---- softmax (rows rq and rq+8 of this warp's 16) ----
        float t0 = -1e30f, t1 = -1e30f;
        #pragma unroll
        for (int n = 0; n < 8; n++) {
            t0 = fmaxf(t0, fmaxf(acc[n][0], acc[n][1]));
            t1 = fmaxf(t1, fmaxf(acc[n][2], acc[n][3]));
        }
        t0 = fmaxf(t0, __shfl_xor_sync(0xffffffffu, t0, 1));
        t0 = fmaxf(t0, __shfl_xor_sync(0xffffffffu, t0, 2));
        t1 = fmaxf(t1, __shfl_xor_sync(0xffffffffu, t1, 1));
        t1 = fmaxf(t1, __shfl_xor_sync(0xffffffffu, t1, 2));
        float mn0 = fmaxf(m0, t0), mn1 = fmaxf(m1, t1);
        float c0 = __expf(m0 - mn0), c1 = __expf(m1 - mn1);
        m0 = mn0; m1 = mn1;
        l0 *= c0; l1 *= c1;
        #pragma unroll
        for (int n = 0; n < 8; n++) {
            o[n][0] *= c0; o[n][1] *= c0; o[n][2] *= c1; o[n][3] *= c1;
        }

        float* pr = &Pb[(w * 16 + rq) * AST + kq * 2];
        #pragma unroll
        for (int n = 0; n < 8; n++) {
            float p0 = __expf(acc[n][0] - m0), p1 = __expf(acc[n][1] - m0);
            float p2 = __expf(acc[n][2] - m1), p3 = __expf(acc[n][3] - m1);
            l0 += p0 + p1; l1 += p2 + p3;
            *(float2*)(pr + n * 8)           = make_float2(p0, p1);
            *(float2*)(pr + 8 * AST + n * 8) = make_float2(p2, p3);
        }
        __syncwarp();

        // ---- PV (3-pass; P split in registers) ----
        const float* pa = &Pb[(w * 16 + rq) * AST + kq];
        #pragma unroll
        for (int s = 0; s < 8; s++) {
            float f[4];
            f[0] = pa[s * 8];       f[1] = pa[8 * AST + s * 8];
            f[2] = pa[s * 8 + 4];   f[3] = pa[8 * AST + s * 8 + 4];
            uint32_t ph[4], pl[4];
            #pragma unroll
            for (int j = 0; j < 4; j++) {
                float h = tf32_rna(f[j]);
                ph[j] = FU(h);
                pl[j] = FU(tf32_rna(f[j] - h));
            }
            #pragma unroll
            for (int n = 0; n < 8; n++) {
                int bi = boff + (n * 8 + rq) * AST + s * 8 + kq;
                uint32_t bh0 = FU(VhS[bi]), bh1 = FU(VhS[bi + 4]);
                uint32_t bl0 = FU(VlS[bi]), bl1 = FU(VlS[bi + 4]);
                MMA_TF32(o[n], ph, bh0, bh1);
                MMA_TF32(o[n], ph, bl0, bl1);
                MMA_TF32(o[n], pl, bh0, bh1);
            }
        }
        __syncthreads();

        if (kt + 2 < 16) {
            int t = kt + 2;
            #pragma unroll
            for (int i = 0; i < 4; i++) {
                int idx = i * 256 + tid;
                int row = idx >> 4, sg = idx & 15;
                uint32_t bo = (uint32_t)(boff + row * AST + sg * 4) * 4;
                cp16(smem_u32(KhS) + bo, khg + (size_t)(t * 64 + row) * D_ + sg * 4);
                cp16(smem_u32(KlS) + bo, klg + (size_t)(t * 64 + row) * D_ + sg * 4);
                cp16(smem_u32(VhS) + bo, vhg + (size_t)row * S_ + t * 64 + sg * 4);
                cp16(smem_u32(VlS) + bo, vlg + (size_t)row * S_ + t * 64 + sg * 4);
            }
            CP_COMMIT();
        }
    }

    // ---- epilogue ----
    l0 += __shfl_xor_sync(0xffffffffu, l0, 1);
    l0 += __shfl_xor_sync(0xffffffffu, l0, 2);
    l1 += __shfl_xor_sync(0xffffffffu, l1, 1);
    l1 += __shfl_xor_sync(0xffffffffu, l1, 2);
    float i0 = 1.0f / l0, i1 = 1.0f / l1;
    int nb = nh / NH_, h = nh % NH_;
    int r0g = q0 + w * 16 + rq;
    float* d0 = g_ao + ((size_t)(nb * S_ + r0g)) * C_ + h * 64 + kq * 2;
    float* d1 = d0 + 8 * C_;
    #pragma unroll
    for (int n = 0; n < 8; n++) {
        *(float2*)(d0 + n * 8) = make_float2(o[n][0] * i0, o[n][1] * i0);
        *(float2*)(d1 + n * 8) = make_float2(o[n][2] * i1, o[n][3] * i1);
    }
}

// ---------------- launch ----------------
extern "C" void kernel_launch(void* const* d_in, const int* in_sizes, int n_in,
                              void* d_out, int out_size) {
    const float* x     = (const float*)d_in[0];
    const float* w_qkv = (const float*)d_in[1];
    const float* w_out = (const float*)d_in[2];
    const float* b_out = (const float*)d_in[3];
    float* out = (float*)d_out;

    cudaFuncSetAttribute(mma_gemm, cudaFuncAttributeMaxDynamicSharedMemorySize, GEMM_SMEM);
    cudaFuncSetAttribute(attn_mma, cudaFuncAttributeMaxDynamicSharedMemorySize, ATT2_SMEM);

    transpose_x<<<dim3(S_ / 32, C_ / 32, N_), dim3(32, 8)>>>(x);
    split_wqkv<<<(C3_ * C_ + 255) / 256, 256>>>(w_qkv);
    split_wout<<<(C_ * C_ + 255) / 256, 256>>>(w_out);

    mma_gemm<<<dim3(C3_ / 128, M_ / 128), 256, GEMM_SMEM>>>(0, nullptr, nullptr);

    attn_mma<<<dim3(S_ / 128, N_ * NH_), 256, ATT2_SMEM>>>();

    split_ao<<<(M_ * C_ / 4) / 256, 256>>>();

    mma_gemm<<<dim3(M_ / 128, C_ / 128), 256, GEMM_SMEM>>>(1, b_out, out);
}